// round 10
// baseline (speedup 1.0000x reference)
#include <cuda_runtime.h>
#include <cuda_bf16.h>
#include <math.h>
#include <stdint.h>

#define EPSF 1e-8f
#define MARGINF 0.2f
#define NATT 1280
#define ATT_SLICE 1802240   // 1408*1280, att partial slice stride

typedef __nv_bfloat16 bf16;

// ======================= scratch (no allocation; zero-initialized) =======================
__device__ bf16 g_vidh[4194304], g_vidl[4194304];       // video split (1024x4096)
__device__ bf16 g_wt0h[4194304], g_wt0l[4194304];       // conv0 weight T split
__device__ bf16 g_wt1h[4194304], g_wt1l[4194304];       // conv1 weight T split
__device__ bf16 g_wt2h[4194304], g_wt2l[4194304];       // conv2 weight T split
__device__ bf16 g_vh[1572864],   g_vl[1572864];         // conv outputs split (rows 1344+ stay 0)
__device__ bf16 g_c2ah[524288],  g_c2al[524288];        // conv2 A padded (128x4096; rows 64+ stay 0)
__device__ bf16 g_uh[1572864],   g_ul[1572864];         // u split (rows 1344+ stay 0)
__device__ bf16 g_wdh[1310720],  g_wdl[1310720];        // words split (1280x1024)
__device__ bf16 g_cdh[1048576],  g_cdl[1048576];        // conv1d w split
__device__ bf16 g_fch[1048576],  g_fcl[1048576];        // fc w split
__device__ bf16 g_sth[131072],   g_stl[131072];         // sentences split+pad (128x1024)
__device__ bf16 g_gph[131072],   g_gpl[131072];         // gpre split (128x1024; rows 64+ stay 0)
__device__ float g_part[4194304];                       // split-K partials
__device__ float g_sall[64 * 64 * 21];
__device__ float g_sc[4096];
__device__ float g_G[64 * 400];
__device__ float g_un[1344];
__device__ float g_sn[64];
__device__ float g_gn[64];

// ======================= split kernels =======================
__device__ __forceinline__ void split1(const float* __restrict__ x, bf16* __restrict__ hi,
                                       bf16* __restrict__ lo, int i, int n) {
    float v = (i < n) ? x[i] : 0.f;
    bf16 h = __float2bfloat16(v);
    hi[i] = h;
    lo[i] = __float2bfloat16(v - __bfloat162float(h));
}
__global__ void split_k(const float* __restrict__ x, bf16* __restrict__ hi,
                        bf16* __restrict__ lo, int n, int ntot) {
    int i = blockIdx.x * blockDim.x + threadIdx.x;
    if (i < ntot) split1(x, hi, lo, i, n);
}
__global__ void msplit_k(const float* __restrict__ sent, bf16* __restrict__ sth, bf16* __restrict__ stl,
                         const float* __restrict__ cdw, bf16* __restrict__ cdh, bf16* __restrict__ cdl,
                         const float* __restrict__ fcw, bf16* __restrict__ fch, bf16* __restrict__ fcl) {
    int b = blockIdx.x;
    if (b < 512) {
        int i = b * 256 + threadIdx.x;
        split1(sent, sth, stl, i, 65536);
    } else if (b < 4608) {
        int i = (b - 512) * 256 + threadIdx.x;
        split1(cdw, cdh, cdl, i, 1048576);
    } else {
        int i = (b - 4608) * 256 + threadIdx.x;
        split1(fcw, fch, fcl, i, 1048576);
    }
}
// all 3 conv weights: transpose (O,I,4) -> wt[o][k*1024+i], split hi/lo (plain R8 version)
__global__ void wsplit3_k(const float* __restrict__ w0, bf16* __restrict__ h0, bf16* __restrict__ l0,
                          const float* __restrict__ w1, bf16* __restrict__ h1, bf16* __restrict__ l1,
                          const float* __restrict__ w2, bf16* __restrict__ h2, bf16* __restrict__ l2) {
    int cv = blockIdx.x >> 10, o = blockIdx.x & 1023;
    const float* w = (cv == 0) ? w0 : (cv == 1) ? w1 : w2;
    bf16* hi = (cv == 0) ? h0 : (cv == 1) ? h1 : h2;
    bf16* lo = (cv == 0) ? l0 : (cv == 1) ? l1 : l2;
    const float* wo = w + (size_t)o * 4096;
    for (int q = threadIdx.x; q < 4096; q += blockDim.x) {
        int k = q >> 10, i = q & 1023;
        float v = wo[i * 4 + k];
        bf16 h = __float2bfloat16(v);
        hi[(size_t)o * 4096 + q] = h;
        lo[(size_t)o * 4096 + q] = __float2bfloat16(v - __bfloat162float(h));
    }
}

// ======================= mma.sync / cp.async helpers =======================
__device__ __forceinline__ uint32_t s2u(const void* p) {
    uint32_t a;
    asm("{ .reg .u64 t; cvta.to.shared.u64 t, %1; cvt.u32.u64 %0, t; }" : "=r"(a) : "l"(p));
    return a;
}
__device__ __forceinline__ void ldm4(uint32_t* r, uint32_t addr) {
    asm volatile("ldmatrix.sync.aligned.m8n8.x4.shared.b16 {%0,%1,%2,%3}, [%4];"
                 : "=r"(r[0]), "=r"(r[1]), "=r"(r[2]), "=r"(r[3]) : "r"(addr));
}
__device__ __forceinline__ void mma_bf16(float* c, const uint32_t* a, const uint32_t* b) {
    asm volatile("mma.sync.aligned.m16n8k16.row.col.f32.bf16.bf16.f32 "
                 "{%0,%1,%2,%3}, {%4,%5,%6,%7}, {%8,%9}, {%0,%1,%2,%3};"
                 : "+f"(c[0]), "+f"(c[1]), "+f"(c[2]), "+f"(c[3])
                 : "r"(a[0]), "r"(a[1]), "r"(a[2]), "r"(a[3]), "r"(b[0]), "r"(b[1]));
}
__device__ __forceinline__ void cp32(uint32_t s, const char* g) {
    asm volatile("cp.async.cg.shared.global [%0], [%1], 16;" :: "r"(s), "l"(g));
    asm volatile("cp.async.cg.shared.global [%0], [%1], 16;" :: "r"(s + 16), "l"(g + 16));
}
#define CP_COMMIT() asm volatile("cp.async.commit_group;" ::: "memory")
#define CP_WAIT(n)  asm volatile("cp.async.wait_group %0;" :: "n"(n) : "memory")

// ======================= bf16x3 HMMA split-K GEMM =======================
// TM x 128 tile, BK=32, 512 threads, 3-stage cp.async, one barrier per chunk.
// Inner loop in N-halves with independent B-lo register buffer (WAR-free for ptxas).
template<int TM>
__global__ void __launch_bounds__(512)
gemm_sk(const bf16* __restrict__ Ah_, const bf16* __restrict__ Al_,
        const bf16* __restrict__ Bh_, const bf16* __restrict__ Bl_,
        float* __restrict__ P, int N, int K, int Ks) {
    constexpr int WM = TM / 32;
    constexpr int WN = 16 / WM;
    constexpr int NT = 16 / WN;          // 8 (TM=256) or 4 (TM=128)
    constexpr int NH = NT / 2;           // tiles per half
    constexpr uint32_t SA = (uint32_t)TM * 80u;
    constexpr uint32_t SB = 128u * 80u;
    constexpr uint32_t STG = 2u * SA + 2u * SB;

    extern __shared__ char smem[];
    const uint32_t sbase = s2u(smem);
    const int tid = threadIdx.x, lane = tid & 31, wid = tid >> 5;
    const int warp_m = wid % WM, warp_n = wid / WM;
    const int bm = blockIdx.y * TM, bn = blockIdx.x << 7;
    const int sl = blockIdx.z;
    const int M = gridDim.y * TM;
    P += (size_t)sl * M * N;

    const size_t K2 = (size_t)K * 2;
    const size_t k0b = (size_t)sl * Ks * 2;
    const uint32_t coloff = (uint32_t)(tid & 1) * 32u;

    const char *pA0, *pA1 = nullptr, *pB;
    uint32_t sA0, sA1 = 0, sBo;
    if (TM == 256) {
        int arow = tid >> 1;
        pA0 = (const char*)Ah_ + (size_t)(bm + arow) * K2 + coloff + k0b;
        sA0 = arow * 80u + coloff;
        pA1 = (const char*)Al_ + (size_t)(bm + arow) * K2 + coloff + k0b;
        sA1 = SA + arow * 80u + coloff;
        int brow = arow & 127;
        pB = (const char*)(tid < 256 ? Bh_ : Bl_) + (size_t)(bn + brow) * K2 + coloff + k0b;
        sBo = 2u * SA + (tid < 256 ? 0u : SB) + brow * 80u + coloff;
    } else {
        int arow = (tid >> 1) & 127;
        pA0 = (const char*)(tid < 256 ? Ah_ : Al_) + (size_t)(bm + arow) * K2 + coloff + k0b;
        sA0 = (tid < 256 ? 0u : SA) + arow * 80u + coloff;
        pB = (const char*)(tid < 256 ? Bh_ : Bl_) + (size_t)(bn + arow) * K2 + coloff + k0b;
        sBo = 2u * SA + (tid < 256 ? 0u : SB) + arow * 80u + coloff;
    }

    const uint32_t a_off = (uint32_t)((warp_m * 32 + (lane & 15)) * 80 + (lane & 16));
    const uint32_t b_row = (uint32_t)(warp_n * (NT * 8) + (lane & 7) + ((lane & 16) ? 8 : 0));
    const uint32_t b_off = 2u * SA + b_row * 80u + ((lane & 8) ? 16u : 0u);

    float acc[2][NT][4];
#pragma unroll
    for (int mt = 0; mt < 2; mt++)
#pragma unroll
        for (int nt = 0; nt < NT; nt++)
#pragma unroll
            for (int q = 0; q < 4; q++) acc[mt][nt][q] = 0.f;

    const int nch = Ks >> 5;
    cp32(sbase + sA0, pA0);
    if (TM == 256) cp32(sbase + sA1, pA1);
    cp32(sbase + sBo, pB);
    CP_COMMIT();
    if (nch > 1) {
        cp32(sbase + STG + sA0, pA0 + 64);
        if (TM == 256) cp32(sbase + STG + sA1, pA1 + 64);
        cp32(sbase + STG + sBo, pB + 64);
        CP_COMMIT();
    }

    for (int c = 0; c < nch; c++) {
        if (c + 1 < nch) { CP_WAIT(1); } else { CP_WAIT(0); }
        __syncthreads();
        if (c + 2 < nch) {
            const size_t koff = (size_t)(c + 2) * 64;
            const uint32_t sb = sbase + (uint32_t)((c + 2) % 3) * STG;
            cp32(sb + sA0, pA0 + koff);
            if (TM == 256) cp32(sb + sA1, pA1 + koff);
            cp32(sb + sBo, pB + koff);
            CP_COMMIT();
        }
        const uint32_t buf = sbase + (uint32_t)(c % 3) * STG;
#pragma unroll
        for (int ks = 0; ks < 2; ks++) {
            const uint32_t kb = (uint32_t)ks * 32u;
            uint32_t aH[2][4], aL[2][4];
#pragma unroll
            for (int mt = 0; mt < 2; mt++) {
                ldm4(aH[mt], buf + a_off + (uint32_t)(mt * 16) * 80u + kb);
                ldm4(aL[mt], buf + SA + a_off + (uint32_t)(mt * 16) * 80u + kb);
            }
#pragma unroll
            for (int h = 0; h < 2; h++) {
                uint32_t bh[NH][2], bl[NH][2];
#pragma unroll
                for (int g = 0; g < NH / 2; g++)
                    ldm4(&bh[g * 2][0],
                         buf + b_off + (uint32_t)((h * NH / 2 + g) * 16) * 80u + kb);
#pragma unroll
                for (int g = 0; g < NH / 2; g++)
                    ldm4(&bl[g * 2][0],
                         buf + SB + b_off + (uint32_t)((h * NH / 2 + g) * 16) * 80u + kb);
#pragma unroll
                for (int mt = 0; mt < 2; mt++)
#pragma unroll
                    for (int nt = 0; nt < NH; nt++)
                        mma_bf16(acc[mt][h * NH + nt], aH[mt], bh[nt]);
#pragma unroll
                for (int mt = 0; mt < 2; mt++)
#pragma unroll
                    for (int nt = 0; nt < NH; nt++)
                        mma_bf16(acc[mt][h * NH + nt], aL[mt], bh[nt]);
#pragma unroll
                for (int mt = 0; mt < 2; mt++)
#pragma unroll
                    for (int nt = 0; nt < NH; nt++)
                        mma_bf16(acc[mt][h * NH + nt], aH[mt], bl[nt]);
            }
        }
    }

    const int r0 = bm + warp_m * 32 + (lane >> 2);
    const int c0 = bn + warp_n * (NT * 8) + (lane & 3) * 2;
#pragma unroll
    for (int mt = 0; mt < 2; mt++) {
#pragma unroll
        for (int nt = 0; nt < NT; nt++) {
            int col = c0 + nt * 8;
            float2 u0, u1;
            u0.x = acc[mt][nt][0]; u0.y = acc[mt][nt][1];
            u1.x = acc[mt][nt][2]; u1.y = acc[mt][nt][3];
            *(float2*)(P + (size_t)(r0 + mt * 16) * N + col) = u0;
            *(float2*)(P + (size_t)(r0 + mt * 16 + 8) * N + col) = u1;
        }
    }
}

// ======================= finish: sum slices + bias + relu + split =======================
template<bool RELU, bool BIAS>
__global__ void finish_k(const float* __restrict__ P, int S, int MNused, int MNfull,
                         const float* __restrict__ bias,
                         float* __restrict__ f32o,
                         bf16* __restrict__ hi, bf16* __restrict__ lo,
                         bf16* __restrict__ hi2, bf16* __restrict__ lo2) {
    int i = blockIdx.x * blockDim.x + threadIdx.x;
    if (i >= MNused) return;
    float a = P[i];
    for (int s = 1; s < S; s++) a += P[(size_t)s * MNfull + i];
    if (BIAS) a += bias[i & 1023];
    if (RELU) a = fmaxf(a, 0.f);
    if (f32o) f32o[i] = a;
    if (hi) {
        bf16 h = __float2bfloat16(a);
        bf16 l = __float2bfloat16(a - __bfloat162float(h));
        hi[i] = h; lo[i] = l;
        if (hi2) { hi2[i] = h; lo2[i] = l; }
    }
}

// ======================= fused finish + row L2 norm (N=1024, one block/row) ============
__global__ void finishrow_k(const float* __restrict__ P, int S, int MNfull,
                            const float* __restrict__ bias,
                            bf16* __restrict__ hi, bf16* __restrict__ lo,
                            float* __restrict__ norm) {
    int r = blockIdx.x;
    const float* p = P + (size_t)r * 1024;
    float sq = 0.f;
#pragma unroll
    for (int j = 0; j < 4; j++) {
        int k = threadIdx.x + j * 256;
        float a = p[k];
        for (int s = 1; s < S; s++) a += p[(size_t)s * MNfull + k];
        a += bias[k];
        bf16 h = __float2bfloat16(a);
        hi[(size_t)r * 1024 + k] = h;
        lo[(size_t)r * 1024 + k] = __float2bfloat16(a - __bfloat162float(h));
        sq += a * a;
    }
    __shared__ float red[256];
    red[threadIdx.x] = sq; __syncthreads();
    for (int off = 128; off > 0; off >>= 1) {
        if (threadIdx.x < off) red[threadIdx.x] += red[threadIdx.x + off];
        __syncthreads();
    }
    if (threadIdx.x == 0) norm[r] = fmaxf(sqrtf(red[0]), EPSF);
}

// ======================= epilogue kernels =======================
__global__ void rownorm_k(const float* __restrict__ X, float* __restrict__ out, int K) {
    int r = blockIdx.x;
    const float* x = X + (size_t)r * K;
    float s = 0.f;
    for (int k = threadIdx.x; k < K; k += blockDim.x) { float v = x[k]; s += v * v; }
    __shared__ float red[256];
    red[threadIdx.x] = s; __syncthreads();
    for (int off = 128; off > 0; off >>= 1) {
        if (threadIdx.x < off) red[threadIdx.x] += red[threadIdx.x + off];
        __syncthreads();
    }
    if (threadIdx.x == 0) out[r] = fmaxf(sqrtf(red[0]), EPSF);
}

__global__ void gram_k(const float* __restrict__ words, float* __restrict__ G) {
    int i = blockIdx.x;
    int warp = threadIdx.x >> 5, lane = threadIdx.x & 31;
    const float4* base = (const float4*)(words + (size_t)i * 20480);
    for (int p = warp; p < 400; p += 8) {
        int w = p / 20, w2 = p % 20;
        const float4* x = base + w * 256;
        const float4* y = base + w2 * 256;
        float s = 0.f;
#pragma unroll
        for (int k = lane; k < 256; k += 32) {
            float4 a = x[k], b = y[k];
            s += a.x * b.x + a.y * b.y + a.z * b.z + a.w * b.w;
        }
        for (int off = 16; off; off >>= 1) s += __shfl_down_sync(0xffffffffu, s, off);
        if (lane == 0) G[i * 400 + p] = s;
    }
}

// sums the S=2 att partial slices inline (no finish pass for att)
__global__ void __launch_bounds__(672)
sim_k(const float* __restrict__ attp, const float* __restrict__ G,
      const float* __restrict__ un, const int* __restrict__ wmask,
      float* __restrict__ sall) {
    int i = blockIdx.x;
    __shared__ float Gs[400];
    __shared__ float mk[20];
    for (int p = threadIdx.x; p < 400; p += 672) Gs[p] = G[i * 400 + p];
    if (threadIdx.x < 20)
        mk[threadIdx.x] = (wmask[i * 20 + threadIdx.x] > 0) ? 0.f : -1e30f;
    __syncthreads();
    for (int item = threadIdx.x; item < 1344; item += 672) {
        int j = item / 21, t = item % 21;
        int r;
        if (t < 16)       r = j * 16 + t;
        else if (t < 20)  r = 1024 + j * 4 + (t - 16);
        else              r = 1280 + j;
        const float* a0 = attp + (size_t)r * NATT + i * 20;
        const float* a1 = a0 + ATT_SLICE;
        float a[20], am[20], e[20];
        float m = -1e38f;
#pragma unroll
        for (int w = 0; w < 20; w++) {
            a[w] = a0[w] + a1[w];
            am[w] = a[w] + mk[w];
            m = fmaxf(m, am[w]);
        }
        float s = 0.f;
#pragma unroll
        for (int w = 0; w < 20; w++) { e[w] = expf(am[w] - m); s += e[w]; }
        float inv = 1.f / s;
        float num = 0.f;
#pragma unroll
        for (int w = 0; w < 20; w++) { e[w] *= inv; num += e[w] * a[w]; }
        float den2 = 0.f;
#pragma unroll
        for (int w = 0; w < 20; w++) {
            float q = 0.f;
#pragma unroll
            for (int w2 = 0; w2 < 20; w2++) q += e[w2] * Gs[w * 20 + w2];
            den2 += e[w] * q;
        }
        float sim = num / (un[r] * fmaxf(sqrtf(den2), EPSF));
        sall[((size_t)i * 64 + j) * 21 + t] = sim;
    }
}

__global__ void scores_k(const float* __restrict__ sall, float* __restrict__ sc,
                         float* __restrict__ out) {
    int idx = blockIdx.x * blockDim.x + threadIdx.x;
    if (idx >= 4096) return;
    const float* p = sall + (size_t)idx * 21;
    float s = 0.f;
#pragma unroll
    for (int t = 0; t < 21; t++) s += p[t];
    sc[idx] = s * (1.f / 21.f);
    int i = idx >> 6, j = idx & 63;
    if (i == j) {
#pragma unroll
        for (int t = 0; t < 21; t++) out[1 + i * 21 + t] = p[t];
    }
}

// gsp = raw split-K partials of the global GEMM: 32 slices of 128x128
__global__ void loss_k(const float* __restrict__ sc, const float* __restrict__ gsp,
                       const float* __restrict__ sn, const float* __restrict__ gn,
                       float* __restrict__ out) {
    __shared__ float ds[64], dg[64], isn[64], ign[64];
    __shared__ float gsum[4096];
    int tid = threadIdx.x;
    // sum 32 slices into smem (64x64 block of each 128x128 slice)
    for (int idx = tid; idx < 4096; idx += blockDim.x) {
        int i = idx >> 6, j = idx & 63;
        float g = 0.f;
#pragma unroll 8
        for (int s = 0; s < 32; s++) g += gsp[s * 16384 + i * 128 + j];
        gsum[idx] = g;
    }
    __syncthreads();
    if (tid < 64) {
        ds[tid] = sc[tid * 65];
        isn[tid] = 1.f / sn[tid];
        ign[tid] = 1.f / gn[tid];
        dg[tid] = gsum[tid * 65] * (1.f / (sn[tid] * gn[tid]));
    }
    __syncthreads();
    float acc = 0.f;
    for (int idx = tid; idx < 4096; idx += blockDim.x) {
        int i = idx >> 6, j = idx & 63;
        if (i == j) continue;
        float s = sc[idx];
        acc += fmaxf(MARGINF + s - ds[i], 0.f) + fmaxf(MARGINF + s - ds[j], 0.f);
        float g = gsum[idx] * isn[i] * ign[j];
        acc += fmaxf(MARGINF + g - dg[i], 0.f) + fmaxf(MARGINF + g - dg[j], 0.f);
    }
    __shared__ float red[256];
    red[tid] = acc; __syncthreads();
    for (int off = 128; off; off >>= 1) {
        if (tid < off) red[tid] += red[tid + off];
        __syncthreads();
    }
    if (tid == 0) out[0] = red[0] * (1.f / 64.f);
}

// ======================= launch =======================
#define SMEM256 184320
#define SMEM128 122880

extern "C" void kernel_launch(void* const* d_in, const int* in_sizes, int n_in,
                              void* d_out, int out_size) {
    const float* video = (const float*)d_in[0];
    const float* words = (const float*)d_in[1];
    const int*   wmask = (const int*)d_in[2];
    const float* sent  = (const float*)d_in[3];
    const float* c0w = (const float*)d_in[4];  const float* c0b = (const float*)d_in[5];
    const float* c1w = (const float*)d_in[6];  const float* c1b = (const float*)d_in[7];
    const float* c2w = (const float*)d_in[8];  const float* c2b = (const float*)d_in[9];
    const float* cdw = (const float*)d_in[10]; const float* cdb = (const float*)d_in[11];
    const float* fcw = (const float*)d_in[12]; const float* fcb = (const float*)d_in[13];
    float* out = (float*)d_out;
    (void)in_sizes; (void)n_in; (void)out_size;

    cudaFuncSetAttribute(gemm_sk<256>, cudaFuncAttributeMaxDynamicSharedMemorySize, SMEM256);
    cudaFuncSetAttribute(gemm_sk<128>, cudaFuncAttributeMaxDynamicSharedMemorySize, SMEM128);

    bf16 *vidh, *vidl, *wt0h, *wt0l, *wt1h, *wt1l, *wt2h, *wt2l, *vh, *vl, *c2ah, *c2al;
    bf16 *uh, *ul, *wdh, *wdl, *cdh, *cdl, *fch, *fcl, *sth, *stl, *gph, *gpl;
    float *part, *sall, *sc, *G, *un, *sn, *gn;
    cudaGetSymbolAddress((void**)&vidh, g_vidh); cudaGetSymbolAddress((void**)&vidl, g_vidl);
    cudaGetSymbolAddress((void**)&wt0h, g_wt0h); cudaGetSymbolAddress((void**)&wt0l, g_wt0l);
    cudaGetSymbolAddress((void**)&wt1h, g_wt1h); cudaGetSymbolAddress((void**)&wt1l, g_wt1l);
    cudaGetSymbolAddress((void**)&wt2h, g_wt2h); cudaGetSymbolAddress((void**)&wt2l, g_wt2l);
    cudaGetSymbolAddress((void**)&vh, g_vh);     cudaGetSymbolAddress((void**)&vl, g_vl);
    cudaGetSymbolAddress((void**)&c2ah, g_c2ah); cudaGetSymbolAddress((void**)&c2al, g_c2al);
    cudaGetSymbolAddress((void**)&uh, g_uh);     cudaGetSymbolAddress((void**)&ul, g_ul);
    cudaGetSymbolAddress((void**)&wdh, g_wdh);   cudaGetSymbolAddress((void**)&wdl, g_wdl);
    cudaGetSymbolAddress((void**)&cdh, g_cdh);   cudaGetSymbolAddress((void**)&cdl, g_cdl);
    cudaGetSymbolAddress((void**)&fch, g_fch);   cudaGetSymbolAddress((void**)&fcl, g_fcl);
    cudaGetSymbolAddress((void**)&sth, g_sth);   cudaGetSymbolAddress((void**)&stl, g_stl);
    cudaGetSymbolAddress((void**)&gph, g_gph);   cudaGetSymbolAddress((void**)&gpl, g_gpl);
    cudaGetSymbolAddress((void**)&part, g_part);
    cudaGetSymbolAddress((void**)&sall, g_sall); cudaGetSymbolAddress((void**)&sc, g_sc);
    cudaGetSymbolAddress((void**)&G, g_G);       cudaGetSymbolAddress((void**)&un, g_un);
    cudaGetSymbolAddress((void**)&sn, g_sn);     cudaGetSymbolAddress((void**)&gn, g_gn);

    // 1..3: minimal prep so launch #4 is the conv0 GEMM (ncu capture slot)
    split_k<<<16384, 256>>>(video, vidh, vidl, 4194304, 4194304);
    wsplit3_k<<<3072, 256>>>(c0w, wt0h, wt0l, c1w, wt1h, wt1l, c2w, wt2h, wt2l);
    split_k<<<5120, 256>>>(words, wdh, wdl, 1310720, 1310720);

    // 4: conv0 GEMM: M=1024 N=1024 K=4096, S=4 Ks=1024 (128 CTAs)
    gemm_sk<256><<<dim3(8, 4, 4), 512, SMEM256>>>(vidh, vidl, wt0h, wt0l, part, 1024, 4096, 1024);

    // other independent prep
    msplit_k<<<8704, 256>>>(sent, sth, stl, cdw, cdh, cdl, fcw, fch, fcl);
    rownorm_k<<<64, 256>>>(sent, sn, 1024);
    gram_k<<<64, 256>>>(words, G);

    finish_k<true, true><<<4096, 256>>>(part, 4, 1048576, 1048576, c0b,
                                        nullptr, vh, vl, nullptr, nullptr);

    // conv1: M=256 N=1024 K=4096, S=16 Ks=256 (128 CTAs); dup into conv2 A view
    gemm_sk<256><<<dim3(8, 1, 16), 512, SMEM256>>>(vh, vl, wt1h, wt1l, part, 1024, 4096, 256);
    finish_k<true, true><<<1024, 256>>>(part, 16, 262144, 262144, c1b,
                                        nullptr, vh + 1048576, vl + 1048576, c2ah, c2al);

    // conv2: M=128 (64 valid + 64 zero pad) N=1024 K=4096, S=16 Ks=256
    gemm_sk<128><<<dim3(8, 1, 16), 512, SMEM128>>>(c2ah, c2al, wt2h, wt2l, part, 1024, 4096, 256);
    finish_k<true, true><<<256, 256>>>(part, 16, 65536, 131072, c2b,
                                       nullptr, vh + 1310720, vl + 1310720, nullptr, nullptr);

    // fc: M=128 N=1024 K=1024, S=16 Ks=64 (128 CTAs); fused finish+norm -> gph/gpl, gn
    gemm_sk<128><<<dim3(8, 1, 16), 512, SMEM128>>>(vh + 1310720, vl + 1310720, fch, fcl,
                                                   part, 1024, 1024, 64);
    finishrow_k<<<64, 256>>>(part, 16, 131072, fcb, gph, gpl, gn);

    // conv1d: M=1408 N=1024 K=1024, S=2 Ks=512 (176 CTAs); fused finish+norm -> uh/ul, un
    gemm_sk<128><<<dim3(8, 11, 2), 512, SMEM128>>>(vh, vl, cdh, cdl, part, 1024, 1024, 512);
    finishrow_k<<<1344, 256>>>(part, 2, 1441792, cdb, uh, ul, un);

    // attention logits: M=1408 N=1280 K=1024, S=2 Ks=512 (220 CTAs); partials consumed by sim_k
    gemm_sk<128><<<dim3(10, 11, 2), 512, SMEM128>>>(uh, ul, wdh, wdl, part, 1280, 1024, 512);

    // fused sim (sums att partials inline)
    sim_k<<<64, 672>>>(part, G, un, wmask, sall);
    scores_k<<<16, 256>>>(sall, sc, out);

    // global raw dots: M=128 N=128 K=1024, S=32 Ks=32 (32 CTAs) -> partials into part+hi region?
    // NOTE: part is free now (sim/scores consumed att partials). Reuse base of part.
    gemm_sk<128><<<dim3(1, 1, 32), 512, SMEM128>>>(sth, stl, gph, gpl, part, 128, 1024, 32);

    // loss sums the 32 gsraw slices inline
    loss_k<<<1, 256>>>(sc, part, sn, gn, out);
}

// round 11
// speedup vs baseline: 1.0536x; 1.0536x over previous
#include <cuda_runtime.h>
#include <cuda_bf16.h>
#include <math.h>
#include <stdint.h>

#define EPSF 1e-8f
#define MARGINF 0.2f
#define NATT 1280

typedef __nv_bfloat16 bf16;

// ======================= scratch (no allocation; zero-initialized) =======================
__device__ bf16 g_vidh[4194304], g_vidl[4194304];       // video split (1024x4096)
__device__ bf16 g_wt0h[4194304], g_wt0l[4194304];       // conv0 weight T split
__device__ bf16 g_wt1h[4194304], g_wt1l[4194304];       // conv1 weight T split
__device__ bf16 g_wt2h[4194304], g_wt2l[4194304];       // conv2 weight T split
__device__ bf16 g_vh[1572864],   g_vl[1572864];         // conv outputs split (rows 1344+ stay 0)
__device__ bf16 g_c2ah[524288],  g_c2al[524288];        // conv2 A padded (128x4096; rows 64+ stay 0)
__device__ bf16 g_uh[1572864],   g_ul[1572864];         // u split (rows 1344+ stay 0)
__device__ bf16 g_wdh[1310720],  g_wdl[1310720];        // words split (1280x1024)
__device__ bf16 g_cdh[1048576],  g_cdl[1048576];        // conv1d w split
__device__ bf16 g_fch[1048576],  g_fcl[1048576];        // fc w split
__device__ bf16 g_sth[131072],   g_stl[131072];         // sentences split+pad (128x1024)
__device__ bf16 g_gph[131072],   g_gpl[131072];         // gpre split (128x1024; rows 64+ stay 0)
__device__ float g_part[4194304];                       // split-K partials
__device__ float g_att[1720320];                        // attention logits (1344x1280)
__device__ float g_gsraw[16384];                        // 128x128 (top 64x64 valid)
__device__ float g_sall[64 * 64 * 21];
__device__ float g_sc[4096];
__device__ float g_G[64 * 400];
__device__ float g_un[1344];
__device__ float g_sn[64];
__device__ float g_gn[64];

// ======================= split kernels =======================
__device__ __forceinline__ void split1(const float* __restrict__ x, bf16* __restrict__ hi,
                                       bf16* __restrict__ lo, int i, int n) {
    float v = (i < n) ? x[i] : 0.f;
    bf16 h = __float2bfloat16(v);
    hi[i] = h;
    lo[i] = __float2bfloat16(v - __bfloat162float(h));
}
__global__ void split_k(const float* __restrict__ x, bf16* __restrict__ hi,
                        bf16* __restrict__ lo, int n, int ntot) {
    int i = blockIdx.x * blockDim.x + threadIdx.x;
    if (i < ntot) split1(x, hi, lo, i, n);
}
__global__ void msplit_k(const float* __restrict__ sent, bf16* __restrict__ sth, bf16* __restrict__ stl,
                         const float* __restrict__ cdw, bf16* __restrict__ cdh, bf16* __restrict__ cdl,
                         const float* __restrict__ fcw, bf16* __restrict__ fch, bf16* __restrict__ fcl) {
    int b = blockIdx.x;
    if (b < 512) {
        int i = b * 256 + threadIdx.x;
        split1(sent, sth, stl, i, 65536);
    } else if (b < 4608) {
        int i = (b - 512) * 256 + threadIdx.x;
        split1(cdw, cdh, cdl, i, 1048576);
    } else {
        int i = (b - 4608) * 256 + threadIdx.x;
        split1(fcw, fch, fcl, i, 1048576);
    }
}
// all 3 conv weights: transpose (O,I,4) -> wt[o][k*1024+i], split hi/lo
__global__ void wsplit3_k(const float* __restrict__ w0, bf16* __restrict__ h0, bf16* __restrict__ l0,
                          const float* __restrict__ w1, bf16* __restrict__ h1, bf16* __restrict__ l1,
                          const float* __restrict__ w2, bf16* __restrict__ h2, bf16* __restrict__ l2) {
    int cv = blockIdx.x >> 10, o = blockIdx.x & 1023;
    const float* w = (cv == 0) ? w0 : (cv == 1) ? w1 : w2;
    bf16* hi = (cv == 0) ? h0 : (cv == 1) ? h1 : h2;
    bf16* lo = (cv == 0) ? l0 : (cv == 1) ? l1 : l2;
    const float* wo = w + (size_t)o * 4096;
    for (int q = threadIdx.x; q < 4096; q += blockDim.x) {
        int k = q >> 10, i = q & 1023;
        float v = wo[i * 4 + k];
        bf16 h = __float2bfloat16(v);
        hi[(size_t)o * 4096 + q] = h;
        lo[(size_t)o * 4096 + q] = __float2bfloat16(v - __bfloat162float(h));
    }
}

// ======================= mma.sync / cp.async helpers =======================
__device__ __forceinline__ uint32_t s2u(const void* p) {
    uint32_t a;
    asm("{ .reg .u64 t; cvta.to.shared.u64 t, %1; cvt.u32.u64 %0, t; }" : "=r"(a) : "l"(p));
    return a;
}
__device__ __forceinline__ void ldm4(uint32_t* r, uint32_t addr) {
    asm volatile("ldmatrix.sync.aligned.m8n8.x4.shared.b16 {%0,%1,%2,%3}, [%4];"
                 : "=r"(r[0]), "=r"(r[1]), "=r"(r[2]), "=r"(r[3]) : "r"(addr));
}
__device__ __forceinline__ void mma_bf16(float* c, const uint32_t* a, const uint32_t* b) {
    asm volatile("mma.sync.aligned.m16n8k16.row.col.f32.bf16.bf16.f32 "
                 "{%0,%1,%2,%3}, {%4,%5,%6,%7}, {%8,%9}, {%0,%1,%2,%3};"
                 : "+f"(c[0]), "+f"(c[1]), "+f"(c[2]), "+f"(c[3])
                 : "r"(a[0]), "r"(a[1]), "r"(a[2]), "r"(a[3]), "r"(b[0]), "r"(b[1]));
}
__device__ __forceinline__ void cp32(uint32_t s, const char* g) {
    asm volatile("cp.async.cg.shared.global [%0], [%1], 16;" :: "r"(s), "l"(g));
    asm volatile("cp.async.cg.shared.global [%0], [%1], 16;" :: "r"(s + 16), "l"(g + 16));
}
#define CP_COMMIT() asm volatile("cp.async.commit_group;" ::: "memory")
#define CP_WAIT(n)  asm volatile("cp.async.wait_group %0;" :: "n"(n) : "memory")

// ======================= bf16x3 HMMA split-K GEMM =======================
// TM x 128 tile, BK=32, 512 threads, 3-stage cp.async, one barrier per chunk.
// Warp-parity ks staggering: half the warps run k-steps {0,1}, half {1,0},
// so each SMSP always has mixed LDSM/MMA-phase warps to overlap.
template<int TM>
__global__ void __launch_bounds__(512)
gemm_sk(const bf16* __restrict__ Ah_, const bf16* __restrict__ Al_,
        const bf16* __restrict__ Bh_, const bf16* __restrict__ Bl_,
        float* __restrict__ P, int N, int K, int Ks) {
    constexpr int WM = TM / 32;
    constexpr int WN = 16 / WM;
    constexpr int NT = 16 / WN;
    constexpr uint32_t SA = (uint32_t)TM * 80u;
    constexpr uint32_t SB = 128u * 80u;
    constexpr uint32_t STG = 2u * SA + 2u * SB;

    extern __shared__ char smem[];
    const uint32_t sbase = s2u(smem);
    const int tid = threadIdx.x, lane = tid & 31, wid = tid >> 5;
    const int warp_m = wid % WM, warp_n = wid / WM;
    const int bm = blockIdx.y * TM, bn = blockIdx.x << 7;
    const int sl = blockIdx.z;
    const int M = gridDim.y * TM;
    P += (size_t)sl * M * N;

    const size_t K2 = (size_t)K * 2;
    const size_t k0b = (size_t)sl * Ks * 2;
    const uint32_t coloff = (uint32_t)(tid & 1) * 32u;

    const char *pA0, *pA1 = nullptr, *pB;
    uint32_t sA0, sA1 = 0, sBo;
    if (TM == 256) {
        int arow = tid >> 1;
        pA0 = (const char*)Ah_ + (size_t)(bm + arow) * K2 + coloff + k0b;
        sA0 = arow * 80u + coloff;
        pA1 = (const char*)Al_ + (size_t)(bm + arow) * K2 + coloff + k0b;
        sA1 = SA + arow * 80u + coloff;
        int brow = arow & 127;
        pB = (const char*)(tid < 256 ? Bh_ : Bl_) + (size_t)(bn + brow) * K2 + coloff + k0b;
        sBo = 2u * SA + (tid < 256 ? 0u : SB) + brow * 80u + coloff;
    } else {
        int arow = (tid >> 1) & 127;
        pA0 = (const char*)(tid < 256 ? Ah_ : Al_) + (size_t)(bm + arow) * K2 + coloff + k0b;
        sA0 = (tid < 256 ? 0u : SA) + arow * 80u + coloff;
        pB = (const char*)(tid < 256 ? Bh_ : Bl_) + (size_t)(bn + arow) * K2 + coloff + k0b;
        sBo = 2u * SA + (tid < 256 ? 0u : SB) + arow * 80u + coloff;
    }

    const uint32_t a_off = (uint32_t)((warp_m * 32 + (lane & 15)) * 80 + (lane & 16));
    const uint32_t b_row = (uint32_t)(warp_n * (NT * 8) + (lane & 7) + ((lane & 16) ? 8 : 0));
    const uint32_t b_off = 2u * SA + b_row * 80u + ((lane & 8) ? 16u : 0u);
    const uint32_t ks_x = (uint32_t)(wid & 1) * 32u;   // warp-parity k-step stagger

    float acc[2][NT][4];
#pragma unroll
    for (int mt = 0; mt < 2; mt++)
#pragma unroll
        for (int nt = 0; nt < NT; nt++)
#pragma unroll
            for (int q = 0; q < 4; q++) acc[mt][nt][q] = 0.f;

    const int nch = Ks >> 5;
    // prologue: stages 0 and 1
    cp32(sbase + sA0, pA0);
    if (TM == 256) cp32(sbase + sA1, pA1);
    cp32(sbase + sBo, pB);
    CP_COMMIT();
    if (nch > 1) {
        cp32(sbase + STG + sA0, pA0 + 64);
        if (TM == 256) cp32(sbase + STG + sA1, pA1 + 64);
        cp32(sbase + STG + sBo, pB + 64);
        CP_COMMIT();
    }

    for (int c = 0; c < nch; c++) {
        if (c + 1 < nch) { CP_WAIT(1); } else { CP_WAIT(0); }
        __syncthreads();
        if (c + 2 < nch) {
            const size_t koff = (size_t)(c + 2) * 64;
            const uint32_t sb = sbase + (uint32_t)((c + 2) % 3) * STG;
            cp32(sb + sA0, pA0 + koff);
            if (TM == 256) cp32(sb + sA1, pA1 + koff);
            cp32(sb + sBo, pB + koff);
            CP_COMMIT();
        }
        const uint32_t buf = sbase + (uint32_t)(c % 3) * STG;
#pragma unroll
        for (int ks = 0; ks < 2; ks++) {
            const uint32_t kb = ((uint32_t)ks * 32u) ^ ks_x;   // staggered k-step order
            uint32_t aH[2][4], aL[2][4], bT[NT][2];
#pragma unroll
            for (int mt = 0; mt < 2; mt++) {
                ldm4(aH[mt], buf + a_off + (uint32_t)(mt * 16) * 80u + kb);
                ldm4(aL[mt], buf + SA + a_off + (uint32_t)(mt * 16) * 80u + kb);
            }
#pragma unroll
            for (int g = 0; g < NT / 2; g++)
                ldm4(&bT[g * 2][0], buf + b_off + (uint32_t)(g * 16) * 80u + kb);
            // group 1: aH x Bh
#pragma unroll
            for (int mt = 0; mt < 2; mt++)
#pragma unroll
                for (int nt = 0; nt < NT; nt++)
                    mma_bf16(acc[mt][nt], aH[mt], bT[nt]);
            // group 2: aL x Bh
#pragma unroll
            for (int mt = 0; mt < 2; mt++)
#pragma unroll
                for (int nt = 0; nt < NT; nt++)
                    mma_bf16(acc[mt][nt], aL[mt], bT[nt]);
            // load Bl, then group 3: aH x Bl
#pragma unroll
            for (int g = 0; g < NT / 2; g++)
                ldm4(&bT[g * 2][0], buf + SB + b_off + (uint32_t)(g * 16) * 80u + kb);
#pragma unroll
            for (int mt = 0; mt < 2; mt++)
#pragma unroll
                for (int nt = 0; nt < NT; nt++)
                    mma_bf16(acc[mt][nt], aH[mt], bT[nt]);
        }
    }

    const int r0 = bm + warp_m * 32 + (lane >> 2);
    const int c0 = bn + warp_n * (NT * 8) + (lane & 3) * 2;
#pragma unroll
    for (int mt = 0; mt < 2; mt++) {
#pragma unroll
        for (int nt = 0; nt < NT; nt++) {
            int col = c0 + nt * 8;
            float2 u0, u1;
            u0.x = acc[mt][nt][0]; u0.y = acc[mt][nt][1];
            u1.x = acc[mt][nt][2]; u1.y = acc[mt][nt][3];
            *(float2*)(P + (size_t)(r0 + mt * 16) * N + col) = u0;
            *(float2*)(P + (size_t)(r0 + mt * 16 + 8) * N + col) = u1;
        }
    }
}

// ======================= finish: sum slices + bias + relu + split =======================
template<bool RELU, bool BIAS>
__global__ void finish_k(const float* __restrict__ P, int S, int MNused, int MNfull,
                         const float* __restrict__ bias,
                         float* __restrict__ f32o,
                         bf16* __restrict__ hi, bf16* __restrict__ lo,
                         bf16* __restrict__ hi2, bf16* __restrict__ lo2) {
    int i = blockIdx.x * blockDim.x + threadIdx.x;
    if (i >= MNused) return;
    float a = P[i];
    for (int s = 1; s < S; s++) a += P[(size_t)s * MNfull + i];
    if (BIAS) a += bias[i & 1023];
    if (RELU) a = fmaxf(a, 0.f);
    if (f32o) f32o[i] = a;
    if (hi) {
        bf16 h = __float2bfloat16(a);
        bf16 l = __float2bfloat16(a - __bfloat162float(h));
        hi[i] = h; lo[i] = l;
        if (hi2) { hi2[i] = h; lo2[i] = l; }
    }
}

// ======================= fused finish + row L2 norm (N=1024, one block/row) ============
__global__ void finishrow_k(const float* __restrict__ P, int S, int MNfull,
                            const float* __restrict__ bias,
                            bf16* __restrict__ hi, bf16* __restrict__ lo,
                            float* __restrict__ norm) {
    int r = blockIdx.x;
    const float* p = P + (size_t)r * 1024;
    float sq = 0.f;
#pragma unroll
    for (int j = 0; j < 4; j++) {
        int k = threadIdx.x + j * 256;
        float a = p[k];
        for (int s = 1; s < S; s++) a += p[(size_t)s * MNfull + k];
        a += bias[k];
        bf16 h = __float2bfloat16(a);
        hi[(size_t)r * 1024 + k] = h;
        lo[(size_t)r * 1024 + k] = __float2bfloat16(a - __bfloat162float(h));
        sq += a * a;
    }
    __shared__ float red[256];
    red[threadIdx.x] = sq; __syncthreads();
    for (int off = 128; off > 0; off >>= 1) {
        if (threadIdx.x < off) red[threadIdx.x] += red[threadIdx.x + off];
        __syncthreads();
    }
    if (threadIdx.x == 0) norm[r] = fmaxf(sqrtf(red[0]), EPSF);
}

// ======================= epilogue kernels =======================
__global__ void rownorm_k(const float* __restrict__ X, float* __restrict__ out, int K) {
    int r = blockIdx.x;
    const float* x = X + (size_t)r * K;
    float s = 0.f;
    for (int k = threadIdx.x; k < K; k += blockDim.x) { float v = x[k]; s += v * v; }
    __shared__ float red[256];
    red[threadIdx.x] = s; __syncthreads();
    for (int off = 128; off > 0; off >>= 1) {
        if (threadIdx.x < off) red[threadIdx.x] += red[threadIdx.x + off];
        __syncthreads();
    }
    if (threadIdx.x == 0) out[r] = fmaxf(sqrtf(red[0]), EPSF);
}

__global__ void gram_k(const float* __restrict__ words, float* __restrict__ G) {
    int i = blockIdx.x;
    int warp = threadIdx.x >> 5, lane = threadIdx.x & 31;
    const float4* base = (const float4*)(words + (size_t)i * 20480);
    for (int p = warp; p < 400; p += 8) {
        int w = p / 20, w2 = p % 20;
        const float4* x = base + w * 256;
        const float4* y = base + w2 * 256;
        float s = 0.f;
#pragma unroll
        for (int k = lane; k < 256; k += 32) {
            float4 a = x[k], b = y[k];
            s += a.x * b.x + a.y * b.y + a.z * b.z + a.w * b.w;
        }
        for (int off = 16; off; off >>= 1) s += __shfl_down_sync(0xffffffffu, s, off);
        if (lane == 0) G[i * 400 + p] = s;
    }
}

__global__ void __launch_bounds__(672)
sim_k(const float* __restrict__ att, const float* __restrict__ G,
      const float* __restrict__ un, const int* __restrict__ wmask,
      float* __restrict__ sall) {
    int i = blockIdx.x;
    __shared__ float Gs[400];
    __shared__ float mk[20];
    for (int p = threadIdx.x; p < 400; p += 672) Gs[p] = G[i * 400 + p];
    if (threadIdx.x < 20)
        mk[threadIdx.x] = (wmask[i * 20 + threadIdx.x] > 0) ? 0.f : -1e30f;
    __syncthreads();
    for (int item = threadIdx.x; item < 1344; item += 672) {
        int j = item / 21, t = item % 21;
        int r;
        if (t < 16)       r = j * 16 + t;
        else if (t < 20)  r = 1024 + j * 4 + (t - 16);
        else              r = 1280 + j;
        const float* arow = att + (size_t)r * NATT + i * 20;
        float a[20], am[20], e[20];
        float m = -1e38f;
#pragma unroll
        for (int w = 0; w < 20; w++) { a[w] = arow[w]; am[w] = a[w] + mk[w]; m = fmaxf(m, am[w]); }
        float s = 0.f;
#pragma unroll
        for (int w = 0; w < 20; w++) { e[w] = expf(am[w] - m); s += e[w]; }
        float inv = 1.f / s;
        float num = 0.f;
#pragma unroll
        for (int w = 0; w < 20; w++) { e[w] *= inv; num += e[w] * a[w]; }
        float den2 = 0.f;
#pragma unroll
        for (int w = 0; w < 20; w++) {
            float q = 0.f;
#pragma unroll
            for (int w2 = 0; w2 < 20; w2++) q += e[w2] * Gs[w * 20 + w2];
            den2 += e[w] * q;
        }
        float sim = num / (un[r] * fmaxf(sqrtf(den2), EPSF));
        sall[((size_t)i * 64 + j) * 21 + t] = sim;
    }
}

__global__ void scores_k(const float* __restrict__ sall, float* __restrict__ sc,
                         float* __restrict__ out) {
    int idx = blockIdx.x * blockDim.x + threadIdx.x;
    if (idx >= 4096) return;
    const float* p = sall + (size_t)idx * 21;
    float s = 0.f;
#pragma unroll
    for (int t = 0; t < 21; t++) s += p[t];
    sc[idx] = s * (1.f / 21.f);
    int i = idx >> 6, j = idx & 63;
    if (i == j) {
#pragma unroll
        for (int t = 0; t < 21; t++) out[1 + i * 21 + t] = p[t];
    }
}

// gs row stride 128
__global__ void loss_k(const float* __restrict__ sc, const float* __restrict__ gs,
                       const float* __restrict__ sn, const float* __restrict__ gn,
                       float* __restrict__ out) {
    __shared__ float ds[64], dg[64], isn[64], ign[64];
    int tid = threadIdx.x;
    if (tid < 64) {
        ds[tid] = sc[tid * 65];
        isn[tid] = 1.f / sn[tid];
        ign[tid] = 1.f / gn[tid];
        dg[tid] = gs[tid * 129] * (1.f / (sn[tid] * gn[tid]));
    }
    __syncthreads();
    float acc = 0.f;
    for (int idx = tid; idx < 4096; idx += blockDim.x) {
        int i = idx >> 6, j = idx & 63;
        if (i == j) continue;
        float s = sc[idx];
        acc += fmaxf(MARGINF + s - ds[i], 0.f) + fmaxf(MARGINF + s - ds[j], 0.f);
        float g = gs[i * 128 + j] * isn[i] * ign[j];
        acc += fmaxf(MARGINF + g - dg[i], 0.f) + fmaxf(MARGINF + g - dg[j], 0.f);
    }
    __shared__ float red[256];
    red[tid] = acc; __syncthreads();
    for (int off = 128; off; off >>= 1) {
        if (tid < off) red[tid] += red[tid + off];
        __syncthreads();
    }
    if (tid == 0) out[0] = red[0] * (1.f / 64.f);
}

// ======================= launch =======================
#define SMEM256 184320
#define SMEM128 122880

extern "C" void kernel_launch(void* const* d_in, const int* in_sizes, int n_in,
                              void* d_out, int out_size) {
    const float* video = (const float*)d_in[0];
    const float* words = (const float*)d_in[1];
    const int*   wmask = (const int*)d_in[2];
    const float* sent  = (const float*)d_in[3];
    const float* c0w = (const float*)d_in[4];  const float* c0b = (const float*)d_in[5];
    const float* c1w = (const float*)d_in[6];  const float* c1b = (const float*)d_in[7];
    const float* c2w = (const float*)d_in[8];  const float* c2b = (const float*)d_in[9];
    const float* cdw = (const float*)d_in[10]; const float* cdb = (const float*)d_in[11];
    const float* fcw = (const float*)d_in[12]; const float* fcb = (const float*)d_in[13];
    float* out = (float*)d_out;
    (void)in_sizes; (void)n_in; (void)out_size;

    cudaFuncSetAttribute(gemm_sk<256>, cudaFuncAttributeMaxDynamicSharedMemorySize, SMEM256);
    cudaFuncSetAttribute(gemm_sk<128>, cudaFuncAttributeMaxDynamicSharedMemorySize, SMEM128);

    bf16 *vidh, *vidl, *wt0h, *wt0l, *wt1h, *wt1l, *wt2h, *wt2l, *vh, *vl, *c2ah, *c2al;
    bf16 *uh, *ul, *wdh, *wdl, *cdh, *cdl, *fch, *fcl, *sth, *stl, *gph, *gpl;
    float *part, *att, *gsraw, *sall, *sc, *G, *un, *sn, *gn;
    cudaGetSymbolAddress((void**)&vidh, g_vidh); cudaGetSymbolAddress((void**)&vidl, g_vidl);
    cudaGetSymbolAddress((void**)&wt0h, g_wt0h); cudaGetSymbolAddress((void**)&wt0l, g_wt0l);
    cudaGetSymbolAddress((void**)&wt1h, g_wt1h); cudaGetSymbolAddress((void**)&wt1l, g_wt1l);
    cudaGetSymbolAddress((void**)&wt2h, g_wt2h); cudaGetSymbolAddress((void**)&wt2l, g_wt2l);
    cudaGetSymbolAddress((void**)&vh, g_vh);     cudaGetSymbolAddress((void**)&vl, g_vl);
    cudaGetSymbolAddress((void**)&c2ah, g_c2ah); cudaGetSymbolAddress((void**)&c2al, g_c2al);
    cudaGetSymbolAddress((void**)&uh, g_uh);     cudaGetSymbolAddress((void**)&ul, g_ul);
    cudaGetSymbolAddress((void**)&wdh, g_wdh);   cudaGetSymbolAddress((void**)&wdl, g_wdl);
    cudaGetSymbolAddress((void**)&cdh, g_cdh);   cudaGetSymbolAddress((void**)&cdl, g_cdl);
    cudaGetSymbolAddress((void**)&fch, g_fch);   cudaGetSymbolAddress((void**)&fcl, g_fcl);
    cudaGetSymbolAddress((void**)&sth, g_sth);   cudaGetSymbolAddress((void**)&stl, g_stl);
    cudaGetSymbolAddress((void**)&gph, g_gph);   cudaGetSymbolAddress((void**)&gpl, g_gpl);
    cudaGetSymbolAddress((void**)&part, g_part);
    cudaGetSymbolAddress((void**)&att, g_att);
    cudaGetSymbolAddress((void**)&gsraw, g_gsraw);
    cudaGetSymbolAddress((void**)&sall, g_sall); cudaGetSymbolAddress((void**)&sc, g_sc);
    cudaGetSymbolAddress((void**)&G, g_G);       cudaGetSymbolAddress((void**)&un, g_un);
    cudaGetSymbolAddress((void**)&sn, g_sn);     cudaGetSymbolAddress((void**)&gn, g_gn);

    // 1..3: minimal prep so launch #4 is the conv0 GEMM (ncu capture slot)
    split_k<<<16384, 256>>>(video, vidh, vidl, 4194304, 4194304);
    wsplit3_k<<<3072, 256>>>(c0w, wt0h, wt0l, c1w, wt1h, wt1l, c2w, wt2h, wt2l);
    split_k<<<5120, 256>>>(words, wdh, wdl, 1310720, 1310720);

    // 4: conv0 GEMM: M=1024 N=1024 K=4096, S=4 Ks=1024 (128 CTAs)
    gemm_sk<256><<<dim3(8, 4, 4), 512, SMEM256>>>(vidh, vidl, wt0h, wt0l, part, 1024, 4096, 1024);

    // other independent prep
    msplit_k<<<8704, 256>>>(sent, sth, stl, cdw, cdh, cdl, fcw, fch, fcl);
    rownorm_k<<<64, 256>>>(sent, sn, 1024);
    gram_k<<<64, 256>>>(words, G);

    finish_k<true, true><<<4096, 256>>>(part, 4, 1048576, 1048576, c0b,
                                        nullptr, vh, vl, nullptr, nullptr);

    // conv1: M=256 N=1024 K=4096, S=16 Ks=256 (128 CTAs); dup into conv2 A view
    gemm_sk<256><<<dim3(8, 1, 16), 512, SMEM256>>>(vh, vl, wt1h, wt1l, part, 1024, 4096, 256);
    finish_k<true, true><<<1024, 256>>>(part, 16, 262144, 262144, c1b,
                                        nullptr, vh + 1048576, vl + 1048576, c2ah, c2al);

    // conv2: M=128 (64 valid + 64 zero pad) N=1024 K=4096, S=16 Ks=256
    gemm_sk<128><<<dim3(8, 1, 16), 512, SMEM128>>>(c2ah, c2al, wt2h, wt2l, part, 1024, 4096, 256);
    finish_k<true, true><<<256, 256>>>(part, 16, 65536, 131072, c2b,
                                       nullptr, vh + 1310720, vl + 1310720, nullptr, nullptr);

    // fc: M=128 N=1024 K=1024, S=8 Ks=128 (64 CTAs); fused finish+norm -> gph/gpl, gn
    gemm_sk<128><<<dim3(8, 1, 8), 512, SMEM128>>>(vh + 1310720, vl + 1310720, fch, fcl,
                                                  part, 1024, 1024, 128);
    finishrow_k<<<64, 256>>>(part, 8, 131072, fcb, gph, gpl, gn);

    // conv1d: M=1408 N=1024 K=1024, S=2 Ks=512 (176 CTAs); fused finish+norm -> uh/ul, un
    gemm_sk<128><<<dim3(8, 11, 2), 512, SMEM128>>>(vh, vl, cdh, cdl, part, 1024, 1024, 512);
    finishrow_k<<<1344, 256>>>(part, 2, 1441792, cdb, uh, ul, un);

    // attention logits: M=1408 N=1280 K=1024, S=2 Ks=512 (220 CTAs); 1344 rows finished
    gemm_sk<128><<<dim3(10, 11, 2), 512, SMEM128>>>(uh, ul, wdh, wdl, part, 1280, 1024, 512);
    finish_k<false, false><<<6720, 256>>>(part, 2, 1720320, 1802240, nullptr,
                                          att, nullptr, nullptr, nullptr, nullptr);

    // global raw dots: M=128 N=128 K=1024, S=32 Ks=32 (32 CTAs)
    gemm_sk<128><<<dim3(1, 1, 32), 512, SMEM128>>>(sth, stl, gph, gpl, part, 128, 1024, 32);
    finish_k<false, false><<<64, 256>>>(part, 32, 16384, 16384, nullptr,
                                        gsraw, nullptr, nullptr, nullptr, nullptr);

    // fused sim + reductions
    sim_k<<<64, 672>>>(att, G, un, wmask, sall);
    scores_k<<<16, 256>>>(sall, sc, out);
    loss_k<<<1, 256>>>(sc, gsraw, sn, gn, out);
}

// round 12
// speedup vs baseline: 1.1024x; 1.0463x over previous
#include <cuda_runtime.h>
#include <cuda_bf16.h>
#include <math.h>
#include <stdint.h>

#define EPSF 1e-8f
#define MARGINF 0.2f
#define NATT 1280

typedef __nv_bfloat16 bf16;

// ======================= scratch (no allocation; zero-initialized) =======================
__device__ bf16 g_vidh[4194304], g_vidl[4194304];       // video split (1024x4096)
__device__ bf16 g_wt0h[4194304], g_wt0l[4194304];       // conv0 weight T split
__device__ bf16 g_wt1h[4194304], g_wt1l[4194304];       // conv1 weight T split
__device__ bf16 g_wt2h[4194304], g_wt2l[4194304];       // conv2 weight T split
__device__ bf16 g_vh[1572864],   g_vl[1572864];         // conv outputs split (rows 1344+ stay 0)
__device__ bf16 g_c2ah[524288],  g_c2al[524288];        // conv2 A padded (128x4096; rows 64+ stay 0)
__device__ bf16 g_uh[1572864],   g_ul[1572864];         // u split (rows 1344+ stay 0)
__device__ bf16 g_wdh[1310720],  g_wdl[1310720];        // words split (1280x1024)
__device__ bf16 g_cdh[1048576],  g_cdl[1048576];        // conv1d w split
__device__ bf16 g_fch[1048576],  g_fcl[1048576];        // fc w split
__device__ bf16 g_sth[131072],   g_stl[131072];         // sentences split+pad (128x1024)
__device__ bf16 g_gph[131072],   g_gpl[131072];         // gpre split (128x1024; rows 64+ stay 0)
__device__ float g_part[4194304];                       // split-K partials
__device__ float g_att[1720320];                        // attention logits (1344x1280)
__device__ float g_gsraw[16384];                        // 128x128 (top 64x64 valid)
__device__ float g_sall[64 * 64 * 21];
__device__ float g_sc[4096];
__device__ float g_G[64 * 400];
__device__ float g_un[1344];
__device__ float g_sn[64];
__device__ float g_gn[64];

// part layout for merged launches:
//  conv1d+fc:   2 slices x 1572864 (rows 0..1343 conv1d, 1408..1535 fc)
//  att+gsraw:   att 2 slices x 1966080 ; gsraw 2 slices x 16384 at +3932160
#define CONV1D_SLICE 1572864
#define ATT_SLICE    1966080
#define GS_OFF       3932160

// ======================= split kernels =======================
__device__ __forceinline__ void split1(const float* __restrict__ x, bf16* __restrict__ hi,
                                       bf16* __restrict__ lo, int i, int n) {
    float v = (i < n) ? x[i] : 0.f;
    bf16 h = __float2bfloat16(v);
    hi[i] = h;
    lo[i] = __float2bfloat16(v - __bfloat162float(h));
}
// video + words + sent(pad) + cdw + fcw in one launch
__global__ void bigsplit_k(const float* __restrict__ video, bf16* __restrict__ vidh, bf16* __restrict__ vidl,
                           const float* __restrict__ words, bf16* __restrict__ wdh, bf16* __restrict__ wdl,
                           const float* __restrict__ sent, bf16* __restrict__ sth, bf16* __restrict__ stl,
                           const float* __restrict__ cdw, bf16* __restrict__ cdh, bf16* __restrict__ cdl,
                           const float* __restrict__ fcw, bf16* __restrict__ fch, bf16* __restrict__ fcl) {
    int b = blockIdx.x;
    if (b < 16384) {
        int i = b * 256 + threadIdx.x;
        split1(video, vidh, vidl, i, 4194304);
    } else if (b < 21504) {
        int i = (b - 16384) * 256 + threadIdx.x;
        split1(words, wdh, wdl, i, 1310720);
    } else if (b < 22016) {
        int i = (b - 21504) * 256 + threadIdx.x;
        split1(sent, sth, stl, i, 65536);
    } else if (b < 26112) {
        int i = (b - 22016) * 256 + threadIdx.x;
        split1(cdw, cdh, cdl, i, 1048576);
    } else {
        int i = (b - 26112) * 256 + threadIdx.x;
        split1(fcw, fch, fcl, i, 1048576);
    }
}
// conv weight transpose via smem staging (R8 best-measured version)
__global__ void wsplit3_k(const float* __restrict__ w0, bf16* __restrict__ h0, bf16* __restrict__ l0,
                          const float* __restrict__ w1, bf16* __restrict__ h1, bf16* __restrict__ l1,
                          const float* __restrict__ w2, bf16* __restrict__ h2, bf16* __restrict__ l2) {
    __shared__ float ws[4096 + 128];
    int cv = blockIdx.x >> 10, o = blockIdx.x & 1023;
    const float* w = (cv == 0) ? w0 : (cv == 1) ? w1 : w2;
    bf16* hi = (cv == 0) ? h0 : (cv == 1) ? h1 : h2;
    bf16* lo = (cv == 0) ? l0 : (cv == 1) ? l1 : l2;
    const float* wo = w + (size_t)o * 4096;
    for (int q = threadIdx.x; q < 4096; q += blockDim.x)
        ws[q + (q >> 5)] = wo[q];
    __syncthreads();
    for (int q = threadIdx.x; q < 4096; q += blockDim.x) {
        int k = q >> 10, i = q & 1023;
        int a = i * 4 + k;
        float v = ws[a + (a >> 5)];
        bf16 h = __float2bfloat16(v);
        hi[(size_t)o * 4096 + q] = h;
        lo[(size_t)o * 4096 + q] = __float2bfloat16(v - __bfloat162float(h));
    }
}

// ======================= mma.sync / cp.async helpers =======================
__device__ __forceinline__ uint32_t s2u(const void* p) {
    uint32_t a;
    asm("{ .reg .u64 t; cvta.to.shared.u64 t, %1; cvt.u32.u64 %0, t; }" : "=r"(a) : "l"(p));
    return a;
}
__device__ __forceinline__ void ldm4(uint32_t* r, uint32_t addr) {
    asm volatile("ldmatrix.sync.aligned.m8n8.x4.shared.b16 {%0,%1,%2,%3}, [%4];"
                 : "=r"(r[0]), "=r"(r[1]), "=r"(r[2]), "=r"(r[3]) : "r"(addr));
}
__device__ __forceinline__ void mma_bf16(float* c, const uint32_t* a, const uint32_t* b) {
    asm volatile("mma.sync.aligned.m16n8k16.row.col.f32.bf16.bf16.f32 "
                 "{%0,%1,%2,%3}, {%4,%5,%6,%7}, {%8,%9}, {%0,%1,%2,%3};"
                 : "+f"(c[0]), "+f"(c[1]), "+f"(c[2]), "+f"(c[3])
                 : "r"(a[0]), "r"(a[1]), "r"(a[2]), "r"(a[3]), "r"(b[0]), "r"(b[1]));
}
__device__ __forceinline__ void cp32(uint32_t s, const char* g) {
    asm volatile("cp.async.cg.shared.global [%0], [%1], 16;" :: "r"(s), "l"(g));
    asm volatile("cp.async.cg.shared.global [%0], [%1], 16;" :: "r"(s + 16), "l"(g + 16));
}
#define CP_COMMIT() asm volatile("cp.async.commit_group;" ::: "memory")
#define CP_WAIT(n)  asm volatile("cp.async.wait_group %0;" :: "n"(n) : "memory")

// ======================= bf16x3 HMMA split-K GEMM (R8 inner loop) =======================
// TM x 128 tile, BK=32, 512 threads, 3-stage cp.async, one barrier per chunk.
// Alt path: blocks with blockIdx.y >= ySplit compute a second independent GEMM
// (A2/B2 -> P2 with N2 columns, slice stride stride2, A rows from A2 base).
template<int TM>
__global__ void __launch_bounds__(512)
gemm_sk(const bf16* __restrict__ Ah_, const bf16* __restrict__ Al_,
        const bf16* __restrict__ Bh_, const bf16* __restrict__ Bl_,
        float* __restrict__ P, int N, int K, int Ks,
        const bf16* A2h, const bf16* A2l, const bf16* B2h, const bf16* B2l,
        float* P2, int N2, int stride2, int ySplit) {
    constexpr int WM = TM / 32;
    constexpr int WN = 16 / WM;
    constexpr int NT = 16 / WN;
    constexpr uint32_t SA = (uint32_t)TM * 80u;
    constexpr uint32_t SB = 128u * 80u;
    constexpr uint32_t STG = 2u * SA + 2u * SB;

    const bool alt = ((int)blockIdx.y >= ySplit);
    if (alt && ((int)blockIdx.x << 7) >= N2) return;

    extern __shared__ char smem[];
    const uint32_t sbase = s2u(smem);
    const int tid = threadIdx.x, lane = tid & 31, wid = tid >> 5;
    const int warp_m = wid % WM, warp_n = wid / WM;
    const int bn = blockIdx.x << 7;
    const int sl = blockIdx.z;
    const int bm = alt ? 0 : blockIdx.y * TM;
    const int Nn = alt ? N2 : N;
    const bf16* __restrict__ Ah = alt ? A2h : Ah_;
    const bf16* __restrict__ Al = alt ? A2l : Al_;
    const bf16* __restrict__ Bh = alt ? B2h : Bh_;
    const bf16* __restrict__ Bl = alt ? B2l : Bl_;
    float* Pout = alt ? (P2 + (size_t)sl * stride2)
                      : (P + (size_t)sl * ((size_t)gridDim.y * TM) * N);

    const size_t K2 = (size_t)K * 2;
    const size_t k0b = (size_t)sl * Ks * 2;
    const uint32_t coloff = (uint32_t)(tid & 1) * 32u;

    const char *pA0, *pA1 = nullptr, *pB;
    uint32_t sA0, sA1 = 0, sBo;
    if (TM == 256) {
        int arow = tid >> 1;
        pA0 = (const char*)Ah + (size_t)(bm + arow) * K2 + coloff + k0b;
        sA0 = arow * 80u + coloff;
        pA1 = (const char*)Al + (size_t)(bm + arow) * K2 + coloff + k0b;
        sA1 = SA + arow * 80u + coloff;
        int brow = arow & 127;
        pB = (const char*)(tid < 256 ? Bh : Bl) + (size_t)(bn + brow) * K2 + coloff + k0b;
        sBo = 2u * SA + (tid < 256 ? 0u : SB) + brow * 80u + coloff;
    } else {
        int arow = (tid >> 1) & 127;
        pA0 = (const char*)(tid < 256 ? Ah : Al) + (size_t)(bm + arow) * K2 + coloff + k0b;
        sA0 = (tid < 256 ? 0u : SA) + arow * 80u + coloff;
        pB = (const char*)(tid < 256 ? Bh : Bl) + (size_t)(bn + arow) * K2 + coloff + k0b;
        sBo = 2u * SA + (tid < 256 ? 0u : SB) + arow * 80u + coloff;
    }

    const uint32_t a_off = (uint32_t)((warp_m * 32 + (lane & 15)) * 80 + (lane & 16));
    const uint32_t b_row = (uint32_t)(warp_n * (NT * 8) + (lane & 7) + ((lane & 16) ? 8 : 0));
    const uint32_t b_off = 2u * SA + b_row * 80u + ((lane & 8) ? 16u : 0u);

    float acc[2][NT][4];
#pragma unroll
    for (int mt = 0; mt < 2; mt++)
#pragma unroll
        for (int nt = 0; nt < NT; nt++)
#pragma unroll
            for (int q = 0; q < 4; q++) acc[mt][nt][q] = 0.f;

    const int nch = Ks >> 5;
    cp32(sbase + sA0, pA0);
    if (TM == 256) cp32(sbase + sA1, pA1);
    cp32(sbase + sBo, pB);
    CP_COMMIT();
    if (nch > 1) {
        cp32(sbase + STG + sA0, pA0 + 64);
        if (TM == 256) cp32(sbase + STG + sA1, pA1 + 64);
        cp32(sbase + STG + sBo, pB + 64);
        CP_COMMIT();
    }

    for (int c = 0; c < nch; c++) {
        if (c + 1 < nch) { CP_WAIT(1); } else { CP_WAIT(0); }
        __syncthreads();
        if (c + 2 < nch) {
            const size_t koff = (size_t)(c + 2) * 64;
            const uint32_t sb = sbase + (uint32_t)((c + 2) % 3) * STG;
            cp32(sb + sA0, pA0 + koff);
            if (TM == 256) cp32(sb + sA1, pA1 + koff);
            cp32(sb + sBo, pB + koff);
            CP_COMMIT();
        }
        const uint32_t buf = sbase + (uint32_t)(c % 3) * STG;
#pragma unroll
        for (int ks = 0; ks < 2; ks++) {
            const uint32_t kb = (uint32_t)ks * 32u;
            uint32_t aH[2][4], aL[2][4], bT[NT][2];
#pragma unroll
            for (int mt = 0; mt < 2; mt++) {
                ldm4(aH[mt], buf + a_off + (uint32_t)(mt * 16) * 80u + kb);
                ldm4(aL[mt], buf + SA + a_off + (uint32_t)(mt * 16) * 80u + kb);
            }
#pragma unroll
            for (int g = 0; g < NT / 2; g++)
                ldm4(&bT[g * 2][0], buf + b_off + (uint32_t)(g * 16) * 80u + kb);
#pragma unroll
            for (int mt = 0; mt < 2; mt++)
#pragma unroll
                for (int nt = 0; nt < NT; nt++)
                    mma_bf16(acc[mt][nt], aH[mt], bT[nt]);
#pragma unroll
            for (int mt = 0; mt < 2; mt++)
#pragma unroll
                for (int nt = 0; nt < NT; nt++)
                    mma_bf16(acc[mt][nt], aL[mt], bT[nt]);
#pragma unroll
            for (int g = 0; g < NT / 2; g++)
                ldm4(&bT[g * 2][0], buf + SB + b_off + (uint32_t)(g * 16) * 80u + kb);
#pragma unroll
            for (int mt = 0; mt < 2; mt++)
#pragma unroll
                for (int nt = 0; nt < NT; nt++)
                    mma_bf16(acc[mt][nt], aH[mt], bT[nt]);
        }
    }

    const int r0 = (alt ? 0 : bm) + warp_m * 32 + (lane >> 2);
    const int c0 = bn + warp_n * (NT * 8) + (lane & 3) * 2;
#pragma unroll
    for (int mt = 0; mt < 2; mt++) {
#pragma unroll
        for (int nt = 0; nt < NT; nt++) {
            int col = c0 + nt * 8;
            float2 u0, u1;
            u0.x = acc[mt][nt][0]; u0.y = acc[mt][nt][1];
            u1.x = acc[mt][nt][2]; u1.y = acc[mt][nt][3];
            *(float2*)(Pout + (size_t)(r0 + mt * 16) * Nn + col) = u0;
            *(float2*)(Pout + (size_t)(r0 + mt * 16 + 8) * Nn + col) = u1;
        }
    }
}

// ======================= finish: sum slices + bias + relu + split =======================
template<bool RELU, bool BIAS>
__global__ void finish_k(const float* __restrict__ P, int S, int MNused, int MNfull,
                         const float* __restrict__ bias,
                         float* __restrict__ f32o,
                         bf16* __restrict__ hi, bf16* __restrict__ lo,
                         bf16* __restrict__ hi2, bf16* __restrict__ lo2) {
    int i = blockIdx.x * blockDim.x + threadIdx.x;
    if (i >= MNused) return;
    float a = P[i];
    for (int s = 1; s < S; s++) a += P[(size_t)s * MNfull + i];
    if (BIAS) a += bias[i & 1023];
    if (RELU) a = fmaxf(a, 0.f);
    if (f32o) f32o[i] = a;
    if (hi) {
        bf16 h = __float2bfloat16(a);
        bf16 l = __float2bfloat16(a - __bfloat162float(h));
        hi[i] = h; lo[i] = l;
        if (hi2) { hi2[i] = h; lo2[i] = l; }
    }
}

// ======================= merged finishrow: conv1d rows + fc rows (S=2 fixed) ============
__global__ void finishrow2_k(const float* __restrict__ P,
                             const float* __restrict__ cdb, const float* __restrict__ fcb,
                             bf16* __restrict__ uh, bf16* __restrict__ ul, float* __restrict__ un,
                             bf16* __restrict__ gph, bf16* __restrict__ gpl, float* __restrict__ gn) {
    int r = blockIdx.x;   // 0..1407
    int pr, orow;
    const float* bias;
    bf16 *oh, *ol;
    float* on;
    if (r < 1344) { pr = r; bias = cdb; oh = uh; ol = ul; on = un; orow = r; }
    else { int rf = r - 1344; pr = 1408 + rf; bias = fcb; oh = gph; ol = gpl; on = gn; orow = rf; }
    const float* p = P + (size_t)pr * 1024;
    float sq = 0.f;
#pragma unroll
    for (int j = 0; j < 4; j++) {
        int k = threadIdx.x + j * 256;
        float a = p[k] + p[(size_t)CONV1D_SLICE + k];
        a += bias[k];
        bf16 h = __float2bfloat16(a);
        oh[(size_t)orow * 1024 + k] = h;
        ol[(size_t)orow * 1024 + k] = __float2bfloat16(a - __bfloat162float(h));
        sq += a * a;
    }
    __shared__ float red[256];
    red[threadIdx.x] = sq; __syncthreads();
    for (int off = 128; off > 0; off >>= 1) {
        if (threadIdx.x < off) red[threadIdx.x] += red[threadIdx.x + off];
        __syncthreads();
    }
    if (threadIdx.x == 0) on[orow] = fmaxf(sqrtf(red[0]), EPSF);
}

// ======================= epilogue kernels =======================
__global__ void rownorm_k(const float* __restrict__ X, float* __restrict__ out, int K) {
    int r = blockIdx.x;
    const float* x = X + (size_t)r * K;
    float s = 0.f;
    for (int k = threadIdx.x; k < K; k += blockDim.x) { float v = x[k]; s += v * v; }
    __shared__ float red[256];
    red[threadIdx.x] = s; __syncthreads();
    for (int off = 128; off > 0; off >>= 1) {
        if (threadIdx.x < off) red[threadIdx.x] += red[threadIdx.x + off];
        __syncthreads();
    }
    if (threadIdx.x == 0) out[r] = fmaxf(sqrtf(red[0]), EPSF);
}

__global__ void gram_k(const float* __restrict__ words, float* __restrict__ G) {
    int i = blockIdx.x;
    int warp = threadIdx.x >> 5, lane = threadIdx.x & 31;
    const float4* base = (const float4*)(words + (size_t)i * 20480);
    for (int p = warp; p < 400; p += 8) {
        int w = p / 20, w2 = p % 20;
        const float4* x = base + w * 256;
        const float4* y = base + w2 * 256;
        float s = 0.f;
#pragma unroll
        for (int k = lane; k < 256; k += 32) {
            float4 a = x[k], b = y[k];
            s += a.x * b.x + a.y * b.y + a.z * b.z + a.w * b.w;
        }
        for (int off = 16; off; off >>= 1) s += __shfl_down_sync(0xffffffffu, s, off);
        if (lane == 0) G[i * 400 + p] = s;
    }
}

__global__ void __launch_bounds__(672)
sim_k(const float* __restrict__ att, const float* __restrict__ G,
      const float* __restrict__ un, const int* __restrict__ wmask,
      float* __restrict__ sall) {
    int i = blockIdx.x;
    __shared__ float Gs[400];
    __shared__ float mk[20];
    for (int p = threadIdx.x; p < 400; p += 672) Gs[p] = G[i * 400 + p];
    if (threadIdx.x < 20)
        mk[threadIdx.x] = (wmask[i * 20 + threadIdx.x] > 0) ? 0.f : -1e30f;
    __syncthreads();
    for (int item = threadIdx.x; item < 1344; item += 672) {
        int j = item / 21, t = item % 21;
        int r;
        if (t < 16)       r = j * 16 + t;
        else if (t < 20)  r = 1024 + j * 4 + (t - 16);
        else              r = 1280 + j;
        const float* arow = att + (size_t)r * NATT + i * 20;
        float a[20], am[20], e[20];
        float m = -1e38f;
#pragma unroll
        for (int w = 0; w < 20; w++) { a[w] = arow[w]; am[w] = a[w] + mk[w]; m = fmaxf(m, am[w]); }
        float s = 0.f;
#pragma unroll
        for (int w = 0; w < 20; w++) { e[w] = expf(am[w] - m); s += e[w]; }
        float inv = 1.f / s;
        float num = 0.f;
#pragma unroll
        for (int w = 0; w < 20; w++) { e[w] *= inv; num += e[w] * a[w]; }
        float den2 = 0.f;
#pragma unroll
        for (int w = 0; w < 20; w++) {
            float q = 0.f;
#pragma unroll
            for (int w2 = 0; w2 < 20; w2++) q += e[w2] * Gs[w * 20 + w2];
            den2 += e[w] * q;
        }
        float sim = num / (un[r] * fmaxf(sqrtf(den2), EPSF));
        sall[((size_t)i * 64 + j) * 21 + t] = sim;
    }
}

__global__ void scores_k(const float* __restrict__ sall, float* __restrict__ sc,
                         float* __restrict__ out) {
    int idx = blockIdx.x * blockDim.x + threadIdx.x;
    if (idx >= 4096) return;
    const float* p = sall + (size_t)idx * 21;
    float s = 0.f;
#pragma unroll
    for (int t = 0; t < 21; t++) s += p[t];
    sc[idx] = s * (1.f / 21.f);
    int i = idx >> 6, j = idx & 63;
    if (i == j) {
#pragma unroll
        for (int t = 0; t < 21; t++) out[1 + i * 21 + t] = p[t];
    }
}

// gs row stride 128
__global__ void loss_k(const float* __restrict__ sc, const float* __restrict__ gs,
                       const float* __restrict__ sn, const float* __restrict__ gn,
                       float* __restrict__ out) {
    __shared__ float ds[64], dg[64], isn[64], ign[64];
    int tid = threadIdx.x;
    if (tid < 64) {
        ds[tid] = sc[tid * 65];
        isn[tid] = 1.f / sn[tid];
        ign[tid] = 1.f / gn[tid];
        dg[tid] = gs[tid * 129] * (1.f / (sn[tid] * gn[tid]));
    }
    __syncthreads();
    float acc = 0.f;
    for (int idx = tid; idx < 4096; idx += blockDim.x) {
        int i = idx >> 6, j = idx & 63;
        if (i == j) continue;
        float s = sc[idx];
        acc += fmaxf(MARGINF + s - ds[i], 0.f) + fmaxf(MARGINF + s - ds[j], 0.f);
        float g = gs[i * 128 + j] * isn[i] * ign[j];
        acc += fmaxf(MARGINF + g - dg[i], 0.f) + fmaxf(MARGINF + g - dg[j], 0.f);
    }
    __shared__ float red[256];
    red[tid] = acc; __syncthreads();
    for (int off = 128; off; off >>= 1) {
        if (tid < off) red[tid] += red[tid + off];
        __syncthreads();
    }
    if (tid == 0) out[0] = red[0] * (1.f / 64.f);
}

// ======================= launch =======================
#define SMEM256 184320
#define SMEM128 122880

extern "C" void kernel_launch(void* const* d_in, const int* in_sizes, int n_in,
                              void* d_out, int out_size) {
    const float* video = (const float*)d_in[0];
    const float* words = (const float*)d_in[1];
    const int*   wmask = (const int*)d_in[2];
    const float* sent  = (const float*)d_in[3];
    const float* c0w = (const float*)d_in[4];  const float* c0b = (const float*)d_in[5];
    const float* c1w = (const float*)d_in[6];  const float* c1b = (const float*)d_in[7];
    const float* c2w = (const float*)d_in[8];  const float* c2b = (const float*)d_in[9];
    const float* cdw = (const float*)d_in[10]; const float* cdb = (const float*)d_in[11];
    const float* fcw = (const float*)d_in[12]; const float* fcb = (const float*)d_in[13];
    float* out = (float*)d_out;
    (void)in_sizes; (void)n_in; (void)out_size;

    cudaFuncSetAttribute(gemm_sk<256>, cudaFuncAttributeMaxDynamicSharedMemorySize, SMEM256);
    cudaFuncSetAttribute(gemm_sk<128>, cudaFuncAttributeMaxDynamicSharedMemorySize, SMEM128);

    bf16 *vidh, *vidl, *wt0h, *wt0l, *wt1h, *wt1l, *wt2h, *wt2l, *vh, *vl, *c2ah, *c2al;
    bf16 *uh, *ul, *wdh, *wdl, *cdh, *cdl, *fch, *fcl, *sth, *stl, *gph, *gpl;
    float *part, *att, *gsraw, *sall, *sc, *G, *un, *sn, *gn;
    cudaGetSymbolAddress((void**)&vidh, g_vidh); cudaGetSymbolAddress((void**)&vidl, g_vidl);
    cudaGetSymbolAddress((void**)&wt0h, g_wt0h); cudaGetSymbolAddress((void**)&wt0l, g_wt0l);
    cudaGetSymbolAddress((void**)&wt1h, g_wt1h); cudaGetSymbolAddress((void**)&wt1l, g_wt1l);
    cudaGetSymbolAddress((void**)&wt2h, g_wt2h); cudaGetSymbolAddress((void**)&wt2l, g_wt2l);
    cudaGetSymbolAddress((void**)&vh, g_vh);     cudaGetSymbolAddress((void**)&vl, g_vl);
    cudaGetSymbolAddress((void**)&c2ah, g_c2ah); cudaGetSymbolAddress((void**)&c2al, g_c2al);
    cudaGetSymbolAddress((void**)&uh, g_uh);     cudaGetSymbolAddress((void**)&ul, g_ul);
    cudaGetSymbolAddress((void**)&wdh, g_wdh);   cudaGetSymbolAddress((void**)&wdl, g_wdl);
    cudaGetSymbolAddress((void**)&cdh, g_cdh);   cudaGetSymbolAddress((void**)&cdl, g_cdl);
    cudaGetSymbolAddress((void**)&fch, g_fch);   cudaGetSymbolAddress((void**)&fcl, g_fcl);
    cudaGetSymbolAddress((void**)&sth, g_sth);   cudaGetSymbolAddress((void**)&stl, g_stl);
    cudaGetSymbolAddress((void**)&gph, g_gph);   cudaGetSymbolAddress((void**)&gpl, g_gpl);
    cudaGetSymbolAddress((void**)&part, g_part);
    cudaGetSymbolAddress((void**)&att, g_att);
    cudaGetSymbolAddress((void**)&gsraw, g_gsraw);
    cudaGetSymbolAddress((void**)&sall, g_sall); cudaGetSymbolAddress((void**)&sc, g_sc);
    cudaGetSymbolAddress((void**)&G, g_G);       cudaGetSymbolAddress((void**)&un, g_un);
    cudaGetSymbolAddress((void**)&sn, g_sn);     cudaGetSymbolAddress((void**)&gn, g_gn);

    // 1..3: prep (conv0 GEMM stays launch #4 for the ncu capture slot)
    bigsplit_k<<<30208, 256>>>(video, vidh, vidl, words, wdh, wdl,
                               sent, sth, stl, cdw, cdh, cdl, fcw, fch, fcl);
    wsplit3_k<<<3072, 256>>>(c0w, wt0h, wt0l, c1w, wt1h, wt1l, c2w, wt2h, wt2l);
    rownorm_k<<<64, 256>>>(sent, sn, 1024);

    // 4: conv0 GEMM: M=1024 N=1024 K=4096, S=4 Ks=1024 (128 CTAs)
    gemm_sk<256><<<dim3(8, 4, 4), 512, SMEM256>>>(vidh, vidl, wt0h, wt0l, part, 1024, 4096, 1024,
        nullptr, nullptr, nullptr, nullptr, nullptr, 0, 0, 1 << 20);

    gram_k<<<64, 256>>>(words, G);

    finish_k<true, true><<<4096, 256>>>(part, 4, 1048576, 1048576, c0b,
                                        nullptr, vh, vl, nullptr, nullptr);

    // conv1: M=256 N=1024 K=4096, S=16 Ks=256 (128 CTAs); dup into conv2 A view
    gemm_sk<256><<<dim3(8, 1, 16), 512, SMEM256>>>(vh, vl, wt1h, wt1l, part, 1024, 4096, 256,
        nullptr, nullptr, nullptr, nullptr, nullptr, 0, 0, 1 << 20);
    finish_k<true, true><<<1024, 256>>>(part, 16, 262144, 262144, c1b,
                                        nullptr, vh + 1048576, vl + 1048576, c2ah, c2al);

    // conv2: M=128 (64 valid + pad) N=1024 K=4096, S=16 Ks=256
    gemm_sk<128><<<dim3(8, 1, 16), 512, SMEM128>>>(c2ah, c2al, wt2h, wt2l, part, 1024, 4096, 256,
        nullptr, nullptr, nullptr, nullptr, nullptr, 0, 0, 1 << 20);
    finish_k<true, true><<<256, 256>>>(part, 16, 65536, 131072, c2b,
                                       nullptr, vh + 1310720, vl + 1310720, nullptr, nullptr);

    // conv1d (+ fc folded as y=11): M=1536 grid, N=1024, K=1024, S=2 Ks=512 (192 CTAs)
    gemm_sk<128><<<dim3(8, 12, 2), 512, SMEM128>>>(vh, vl, cdh, cdl, part, 1024, 1024, 512,
        vh + 1310720, vl + 1310720, fch, fcl,
        part + 1408 * 1024, 1024, CONV1D_SLICE, 11);
    // merged finishrow: conv1d rows -> uh/ul/un ; fc rows -> gph/gpl/gn
    finishrow2_k<<<1408, 256>>>(part, cdb, fcb, uh, ul, un, gph, gpl, gn);

    // att (+ gsraw folded as y=11,x=0): N=1280, K=1024, S=2 Ks=512 (222 active CTAs)
    gemm_sk<128><<<dim3(10, 12, 2), 512, SMEM128>>>(uh, ul, wdh, wdl, part, 1280, 1024, 512,
        sth, stl, gph, gpl,
        part + GS_OFF, 128, 16384, 11);
    finish_k<false, false><<<6720, 256>>>(part, 2, 1720320, ATT_SLICE, nullptr,
                                          att, nullptr, nullptr, nullptr, nullptr);
    finish_k<false, false><<<64, 256>>>(part + GS_OFF, 2, 16384, 16384, nullptr,
                                        gsraw, nullptr, nullptr, nullptr, nullptr);

    // fused sim + reductions
    sim_k<<<64, 672>>>(att, G, un, wmask, sall);
    scores_k<<<16, 256>>>(sall, sc, out);
    loss_k<<<1, 256>>>(sc, gsraw, sn, gn, out);
}

// round 13
// speedup vs baseline: 1.3484x; 1.2231x over previous
#include <cuda_runtime.h>
#include <cuda_fp16.h>
#include <math.h>
#include <stdint.h>

#define EPSF 1e-8f
#define MARGINF 0.2f
#define NATT 1280

typedef __half fp16;

// ======================= scratch (no allocation; zero-initialized) =======================
__device__ fp16 g_vidh[4194304], g_vidl[4194304];       // video split A (1024x4096)
__device__ fp16 g_wt0h[4194304];                        // conv0 weight T (B: hi only)
__device__ fp16 g_wt1h[4194304];                        // conv1 weight T
__device__ fp16 g_wt2h[4194304];                        // conv2 weight T
__device__ fp16 g_vh[1572864],   g_vl[1572864];         // conv outputs split A (rows 1344+ stay 0)
__device__ fp16 g_c2ah[524288],  g_c2al[524288];        // conv2 A padded (128x4096; rows 64+ stay 0)
__device__ fp16 g_uh[1572864],   g_ul[1572864];         // u split A (rows 1344+ stay 0)
__device__ fp16 g_wdh[1310720];                         // words (B: hi only)
__device__ fp16 g_cdh[1048576];                         // conv1d w (B)
__device__ fp16 g_fch[1048576];                         // fc w (B)
__device__ fp16 g_sth[131072],   g_stl[131072];         // sentences split A + pad (128x1024)
__device__ fp16 g_gph[131072];                          // gpre (B: hi only; rows 64+ stay 0)
__device__ float g_part[4194304];                       // split-K partials
__device__ float g_att[1720320];                        // attention logits (1344x1280)
__device__ float g_gsraw[16384];                        // 128x128 (top 64x64 valid)
__device__ float g_sall[64 * 64 * 21];
__device__ float g_sc[4096];
__device__ float g_G[64 * 400];
__device__ float g_un[1344];
__device__ float g_sn[64];
__device__ float g_gn[64];

// part layout for merged launches
#define CONV1D_SLICE 1572864
#define ATT_SLICE    1966080
#define GS_OFF       3932160

// ======================= split kernels =======================
__device__ __forceinline__ void split1A(const float* __restrict__ x, fp16* __restrict__ hi,
                                        fp16* __restrict__ lo, int i, int n) {
    float v = (i < n) ? x[i] : 0.f;
    fp16 h = __float2half(v);
    hi[i] = h;
    lo[i] = __float2half(v - __half2float(h));
}
__device__ __forceinline__ void split1B(const float* __restrict__ x, fp16* __restrict__ hi,
                                        int i, int n) {
    float v = (i < n) ? x[i] : 0.f;
    hi[i] = __float2half(v);
}
// video(A) + words(B) + sent(A,pad) + cdw(B) + fcw(B) in one launch
__global__ void bigsplit_k(const float* __restrict__ video, fp16* __restrict__ vidh, fp16* __restrict__ vidl,
                           const float* __restrict__ words, fp16* __restrict__ wdh,
                           const float* __restrict__ sent, fp16* __restrict__ sth, fp16* __restrict__ stl,
                           const float* __restrict__ cdw, fp16* __restrict__ cdh,
                           const float* __restrict__ fcw, fp16* __restrict__ fch) {
    int b = blockIdx.x;
    if (b < 16384) {
        int i = b * 256 + threadIdx.x;
        split1A(video, vidh, vidl, i, 4194304);
    } else if (b < 21504) {
        int i = (b - 16384) * 256 + threadIdx.x;
        split1B(words, wdh, i, 1310720);
    } else if (b < 22016) {
        int i = (b - 21504) * 256 + threadIdx.x;
        split1A(sent, sth, stl, i, 65536);
    } else if (b < 26112) {
        int i = (b - 22016) * 256 + threadIdx.x;
        split1B(cdw, cdh, i, 1048576);
    } else {
        int i = (b - 26112) * 256 + threadIdx.x;
        split1B(fcw, fch, i, 1048576);
    }
}
// conv weight transpose (B side: hi only), smem staged
__global__ void wsplit3_k(const float* __restrict__ w0, fp16* __restrict__ h0,
                          const float* __restrict__ w1, fp16* __restrict__ h1,
                          const float* __restrict__ w2, fp16* __restrict__ h2) {
    __shared__ float ws[4096 + 128];
    int cv = blockIdx.x >> 10, o = blockIdx.x & 1023;
    const float* w = (cv == 0) ? w0 : (cv == 1) ? w1 : w2;
    fp16* hi = (cv == 0) ? h0 : (cv == 1) ? h1 : h2;
    const float* wo = w + (size_t)o * 4096;
    for (int q = threadIdx.x; q < 4096; q += blockDim.x)
        ws[q + (q >> 5)] = wo[q];
    __syncthreads();
    for (int q = threadIdx.x; q < 4096; q += blockDim.x) {
        int k = q >> 10, i = q & 1023;
        int a = i * 4 + k;
        hi[(size_t)o * 4096 + q] = __float2half(ws[a + (a >> 5)]);
    }
}

// ======================= mma.sync / cp.async helpers =======================
__device__ __forceinline__ uint32_t s2u(const void* p) {
    uint32_t a;
    asm("{ .reg .u64 t; cvta.to.shared.u64 t, %1; cvt.u32.u64 %0, t; }" : "=r"(a) : "l"(p));
    return a;
}
__device__ __forceinline__ void ldm4(uint32_t* r, uint32_t addr) {
    asm volatile("ldmatrix.sync.aligned.m8n8.x4.shared.b16 {%0,%1,%2,%3}, [%4];"
                 : "=r"(r[0]), "=r"(r[1]), "=r"(r[2]), "=r"(r[3]) : "r"(addr));
}
__device__ __forceinline__ void mma_fp16(float* c, const uint32_t* a, const uint32_t* b) {
    asm volatile("mma.sync.aligned.m16n8k16.row.col.f32.f16.f16.f32 "
                 "{%0,%1,%2,%3}, {%4,%5,%6,%7}, {%8,%9}, {%0,%1,%2,%3};"
                 : "+f"(c[0]), "+f"(c[1]), "+f"(c[2]), "+f"(c[3])
                 : "r"(a[0]), "r"(a[1]), "r"(a[2]), "r"(a[3]), "r"(b[0]), "r"(b[1]));
}
__device__ __forceinline__ void cp32(uint32_t s, const char* g) {
    asm volatile("cp.async.cg.shared.global [%0], [%1], 16;" :: "r"(s), "l"(g));
    asm volatile("cp.async.cg.shared.global [%0], [%1], 16;" :: "r"(s + 16), "l"(g + 16));
}
#define CP_COMMIT() asm volatile("cp.async.commit_group;" ::: "memory")
#define CP_WAIT(n)  asm volatile("cp.async.wait_group %0;" :: "n"(n) : "memory")

// ======================= fp16x2 HMMA split-K GEMM =======================
// C = (Ah+Al) * Bh. TM x 128 tile, BK=32, 512 threads, 3-stage cp.async,
// one barrier per chunk. Alt path for folded second GEMM (blockIdx.y >= ySplit).
template<int TM>
__global__ void __launch_bounds__(512)
gemm_sk(const fp16* __restrict__ Ah_, const fp16* __restrict__ Al_,
        const fp16* __restrict__ Bh_,
        float* __restrict__ P, int N, int K, int Ks,
        const fp16* A2h, const fp16* A2l, const fp16* B2h,
        float* P2, int N2, int stride2, int ySplit) {
    constexpr int WM = TM / 32;
    constexpr int WN = 16 / WM;
    constexpr int NT = 16 / WN;
    constexpr uint32_t SA = (uint32_t)TM * 80u;
    constexpr uint32_t SB = 128u * 80u;
    constexpr uint32_t STG = 2u * SA + SB;

    const bool alt = ((int)blockIdx.y >= ySplit);
    if (alt && ((int)blockIdx.x << 7) >= N2) return;

    extern __shared__ char smem[];
    const uint32_t sbase = s2u(smem);
    const int tid = threadIdx.x, lane = tid & 31, wid = tid >> 5;
    const int warp_m = wid % WM, warp_n = wid / WM;
    const int bn = blockIdx.x << 7;
    const int sl = blockIdx.z;
    const int bm = alt ? 0 : blockIdx.y * TM;
    const int Nn = alt ? N2 : N;
    const fp16* __restrict__ Ah = alt ? A2h : Ah_;
    const fp16* __restrict__ Al = alt ? A2l : Al_;
    const fp16* __restrict__ Bh = alt ? B2h : Bh_;
    float* Pout = alt ? (P2 + (size_t)sl * stride2)
                      : (P + (size_t)sl * ((size_t)gridDim.y * TM) * N);

    const size_t K2 = (size_t)K * 2;
    const size_t k0b = (size_t)sl * Ks * 2;
    const uint32_t coloff = (uint32_t)(tid & 1) * 32u;
    const bool doB = (tid < 256);

    const char *pA0, *pA1 = nullptr, *pB = nullptr;
    uint32_t sA0, sA1 = 0, sBo = 0;
    if (TM == 256) {
        int arow = tid >> 1;
        pA0 = (const char*)Ah + (size_t)(bm + arow) * K2 + coloff + k0b;
        sA0 = arow * 80u + coloff;
        pA1 = (const char*)Al + (size_t)(bm + arow) * K2 + coloff + k0b;
        sA1 = SA + arow * 80u + coloff;
        if (doB) {
            int brow = tid >> 1;
            pB = (const char*)Bh + (size_t)(bn + brow) * K2 + coloff + k0b;
            sBo = 2u * SA + brow * 80u + coloff;
        }
    } else {
        int arow = (tid >> 1) & 127;
        pA0 = (const char*)(tid < 256 ? Ah : Al) + (size_t)(bm + arow) * K2 + coloff + k0b;
        sA0 = (tid < 256 ? 0u : SA) + arow * 80u + coloff;
        if (doB) {
            int brow = tid >> 1;
            pB = (const char*)Bh + (size_t)(bn + brow) * K2 + coloff + k0b;
            sBo = 2u * SA + brow * 80u + coloff;
        }
    }

    const uint32_t a_off = (uint32_t)((warp_m * 32 + (lane & 15)) * 80 + (lane & 16));
    const uint32_t b_row = (uint32_t)(warp_n * (NT * 8) + (lane & 7) + ((lane & 16) ? 8 : 0));
    const uint32_t b_off = 2u * SA + b_row * 80u + ((lane & 8) ? 16u : 0u);

    float acc[2][NT][4];
#pragma unroll
    for (int mt = 0; mt < 2; mt++)
#pragma unroll
        for (int nt = 0; nt < NT; nt++)
#pragma unroll
            for (int q = 0; q < 4; q++) acc[mt][nt][q] = 0.f;

    const int nch = Ks >> 5;
    cp32(sbase + sA0, pA0);
    if (TM == 256) cp32(sbase + sA1, pA1);
    if (doB) cp32(sbase + sBo, pB);
    CP_COMMIT();
    if (nch > 1) {
        cp32(sbase + STG + sA0, pA0 + 64);
        if (TM == 256) cp32(sbase + STG + sA1, pA1 + 64);
        if (doB) cp32(sbase + STG + sBo, pB + 64);
        CP_COMMIT();
    }

    for (int c = 0; c < nch; c++) {
        if (c + 1 < nch) { CP_WAIT(1); } else { CP_WAIT(0); }
        __syncthreads();
        if (c + 2 < nch) {
            const size_t koff = (size_t)(c + 2) * 64;
            const uint32_t sb = sbase + (uint32_t)((c + 2) % 3) * STG;
            cp32(sb + sA0, pA0 + koff);
            if (TM == 256) cp32(sb + sA1, pA1 + koff);
            if (doB) cp32(sb + sBo, pB + koff);
            CP_COMMIT();
        }
        const uint32_t buf = sbase + (uint32_t)(c % 3) * STG;
#pragma unroll
        for (int ks = 0; ks < 2; ks++) {
            const uint32_t kb = (uint32_t)ks * 32u;
            uint32_t aH[2][4], aL[2][4], bT[NT][2];
#pragma unroll
            for (int mt = 0; mt < 2; mt++) {
                ldm4(aH[mt], buf + a_off + (uint32_t)(mt * 16) * 80u + kb);
                ldm4(aL[mt], buf + SA + a_off + (uint32_t)(mt * 16) * 80u + kb);
            }
#pragma unroll
            for (int g = 0; g < NT / 2; g++)
                ldm4(&bT[g * 2][0], buf + b_off + (uint32_t)(g * 16) * 80u + kb);
#pragma unroll
            for (int mt = 0; mt < 2; mt++)
#pragma unroll
                for (int nt = 0; nt < NT; nt++)
                    mma_fp16(acc[mt][nt], aH[mt], bT[nt]);
#pragma unroll
            for (int mt = 0; mt < 2; mt++)
#pragma unroll
                for (int nt = 0; nt < NT; nt++)
                    mma_fp16(acc[mt][nt], aL[mt], bT[nt]);
        }
    }

    const int r0 = (alt ? 0 : bm) + warp_m * 32 + (lane >> 2);
    const int c0 = bn + warp_n * (NT * 8) + (lane & 3) * 2;
#pragma unroll
    for (int mt = 0; mt < 2; mt++) {
#pragma unroll
        for (int nt = 0; nt < NT; nt++) {
            int col = c0 + nt * 8;
            float2 u0, u1;
            u0.x = acc[mt][nt][0]; u0.y = acc[mt][nt][1];
            u1.x = acc[mt][nt][2]; u1.y = acc[mt][nt][3];
            *(float2*)(Pout + (size_t)(r0 + mt * 16) * Nn + col) = u0;
            *(float2*)(Pout + (size_t)(r0 + mt * 16 + 8) * Nn + col) = u1;
        }
    }
}

// ======================= finish: sum slices + bias + relu + split =======================
template<bool RELU, bool BIAS>
__global__ void finish_k(const float* __restrict__ P, int S, int MNused, int MNfull,
                         const float* __restrict__ bias,
                         float* __restrict__ f32o,
                         fp16* __restrict__ hi, fp16* __restrict__ lo,
                         fp16* __restrict__ hi2, fp16* __restrict__ lo2) {
    int i = blockIdx.x * blockDim.x + threadIdx.x;
    if (i >= MNused) return;
    float a = P[i];
    for (int s = 1; s < S; s++) a += P[(size_t)s * MNfull + i];
    if (BIAS) a += bias[i & 1023];
    if (RELU) a = fmaxf(a, 0.f);
    if (f32o) f32o[i] = a;
    if (hi) {
        fp16 h = __float2half(a);
        fp16 l = __float2half(a - __half2float(h));
        hi[i] = h; lo[i] = l;
        if (hi2) { hi2[i] = h; lo2[i] = l; }
    }
}

// merged finishrow: conv1d rows -> uh/ul/un (A-side) ; fc rows -> gph (B-side) + gn. S=2.
__global__ void finishrow2_k(const float* __restrict__ P,
                             const float* __restrict__ cdb, const float* __restrict__ fcb,
                             fp16* __restrict__ uh, fp16* __restrict__ ul, float* __restrict__ un,
                             fp16* __restrict__ gph, float* __restrict__ gn) {
    int r = blockIdx.x;   // 0..1407
    int pr, orow;
    const float* bias;
    fp16 *oh, *ol;
    float* on;
    if (r < 1344) { pr = r; bias = cdb; oh = uh; ol = ul; on = un; orow = r; }
    else { int rf = r - 1344; pr = 1408 + rf; bias = fcb; oh = gph; ol = nullptr; on = gn; orow = rf; }
    const float* p = P + (size_t)pr * 1024;
    float sq = 0.f;
#pragma unroll
    for (int j = 0; j < 4; j++) {
        int k = threadIdx.x + j * 256;
        float a = p[k] + p[(size_t)CONV1D_SLICE + k];
        a += bias[k];
        fp16 h = __float2half(a);
        oh[(size_t)orow * 1024 + k] = h;
        if (ol) ol[(size_t)orow * 1024 + k] = __float2half(a - __half2float(h));
        sq += a * a;
    }
    __shared__ float red[256];
    red[threadIdx.x] = sq; __syncthreads();
    for (int off = 128; off > 0; off >>= 1) {
        if (threadIdx.x < off) red[threadIdx.x] += red[threadIdx.x + off];
        __syncthreads();
    }
    if (threadIdx.x == 0) on[orow] = fmaxf(sqrtf(red[0]), EPSF);
}

// ======================= epilogue kernels =======================
__global__ void rownorm_k(const float* __restrict__ X, float* __restrict__ out, int K) {
    int r = blockIdx.x;
    const float* x = X + (size_t)r * K;
    float s = 0.f;
    for (int k = threadIdx.x; k < K; k += blockDim.x) { float v = x[k]; s += v * v; }
    __shared__ float red[256];
    red[threadIdx.x] = s; __syncthreads();
    for (int off = 128; off > 0; off >>= 1) {
        if (threadIdx.x < off) red[threadIdx.x] += red[threadIdx.x + off];
        __syncthreads();
    }
    if (threadIdx.x == 0) out[r] = fmaxf(sqrtf(red[0]), EPSF);
}

__global__ void gram_k(const float* __restrict__ words, float* __restrict__ G) {
    int i = blockIdx.x;
    int warp = threadIdx.x >> 5, lane = threadIdx.x & 31;
    const float4* base = (const float4*)(words + (size_t)i * 20480);
    for (int p = warp; p < 400; p += 8) {
        int w = p / 20, w2 = p % 20;
        const float4* x = base + w * 256;
        const float4* y = base + w2 * 256;
        float s = 0.f;
#pragma unroll
        for (int k = lane; k < 256; k += 32) {
            float4 a = x[k], b = y[k];
            s += a.x * b.x + a.y * b.y + a.z * b.z + a.w * b.w;
        }
        for (int off = 16; off; off >>= 1) s += __shfl_down_sync(0xffffffffu, s, off);
        if (lane == 0) G[i * 400 + p] = s;
    }
}

__global__ void __launch_bounds__(672)
sim_k(const float* __restrict__ att, const float* __restrict__ G,
      const float* __restrict__ un, const int* __restrict__ wmask,
      float* __restrict__ sall) {
    int i = blockIdx.x;
    __shared__ float Gs[400];
    __shared__ float mk[20];
    for (int p = threadIdx.x; p < 400; p += 672) Gs[p] = G[i * 400 + p];
    if (threadIdx.x < 20)
        mk[threadIdx.x] = (wmask[i * 20 + threadIdx.x] > 0) ? 0.f : -1e30f;
    __syncthreads();
    for (int item = threadIdx.x; item < 1344; item += 672) {
        int j = item / 21, t = item % 21;
        int r;
        if (t < 16)       r = j * 16 + t;
        else if (t < 20)  r = 1024 + j * 4 + (t - 16);
        else              r = 1280 + j;
        const float* arow = att + (size_t)r * NATT + i * 20;
        float a[20], am[20], e[20];
        float m = -1e38f;
#pragma unroll
        for (int w = 0; w < 20; w++) { a[w] = arow[w]; am[w] = a[w] + mk[w]; m = fmaxf(m, am[w]); }
        float s = 0.f;
#pragma unroll
        for (int w = 0; w < 20; w++) { e[w] = expf(am[w] - m); s += e[w]; }
        float inv = 1.f / s;
        float num = 0.f;
#pragma unroll
        for (int w = 0; w < 20; w++) { e[w] *= inv; num += e[w] * a[w]; }
        float den2 = 0.f;
#pragma unroll
        for (int w = 0; w < 20; w++) {
            float q = 0.f;
#pragma unroll
            for (int w2 = 0; w2 < 20; w2++) q += e[w2] * Gs[w * 20 + w2];
            den2 += e[w] * q;
        }
        float sim = num / (un[r] * fmaxf(sqrtf(den2), EPSF));
        sall[((size_t)i * 64 + j) * 21 + t] = sim;
    }
}

__global__ void scores_k(const float* __restrict__ sall, float* __restrict__ sc,
                         float* __restrict__ out) {
    int idx = blockIdx.x * blockDim.x + threadIdx.x;
    if (idx >= 4096) return;
    const float* p = sall + (size_t)idx * 21;
    float s = 0.f;
#pragma unroll
    for (int t = 0; t < 21; t++) s += p[t];
    sc[idx] = s * (1.f / 21.f);
    int i = idx >> 6, j = idx & 63;
    if (i == j) {
#pragma unroll
        for (int t = 0; t < 21; t++) out[1 + i * 21 + t] = p[t];
    }
}

// gs row stride 128
__global__ void loss_k(const float* __restrict__ sc, const float* __restrict__ gs,
                       const float* __restrict__ sn, const float* __restrict__ gn,
                       float* __restrict__ out) {
    __shared__ float ds[64], dg[64], isn[64], ign[64];
    int tid = threadIdx.x;
    if (tid < 64) {
        ds[tid] = sc[tid * 65];
        isn[tid] = 1.f / sn[tid];
        ign[tid] = 1.f / gn[tid];
        dg[tid] = gs[tid * 129] * (1.f / (sn[tid] * gn[tid]));
    }
    __syncthreads();
    float acc = 0.f;
    for (int idx = tid; idx < 4096; idx += blockDim.x) {
        int i = idx >> 6, j = idx & 63;
        if (i == j) continue;
        float s = sc[idx];
        acc += fmaxf(MARGINF + s - ds[i], 0.f) + fmaxf(MARGINF + s - ds[j], 0.f);
        float g = gs[i * 128 + j] * isn[i] * ign[j];
        acc += fmaxf(MARGINF + g - dg[i], 0.f) + fmaxf(MARGINF + g - dg[j], 0.f);
    }
    __shared__ float red[256];
    red[tid] = acc; __syncthreads();
    for (int off = 128; off; off >>= 1) {
        if (tid < off) red[tid] += red[tid + off];
        __syncthreads();
    }
    if (tid == 0) out[0] = red[0] * (1.f / 64.f);
}

// ======================= launch =======================
#define SMEM256 153600   // 3 * (2*20480 + 10240)
#define SMEM128 92160    // 3 * (2*10240 + 10240)

extern "C" void kernel_launch(void* const* d_in, const int* in_sizes, int n_in,
                              void* d_out, int out_size) {
    const float* video = (const float*)d_in[0];
    const float* words = (const float*)d_in[1];
    const int*   wmask = (const int*)d_in[2];
    const float* sent  = (const float*)d_in[3];
    const float* c0w = (const float*)d_in[4];  const float* c0b = (const float*)d_in[5];
    const float* c1w = (const float*)d_in[6];  const float* c1b = (const float*)d_in[7];
    const float* c2w = (const float*)d_in[8];  const float* c2b = (const float*)d_in[9];
    const float* cdw = (const float*)d_in[10]; const float* cdb = (const float*)d_in[11];
    const float* fcw = (const float*)d_in[12]; const float* fcb = (const float*)d_in[13];
    float* out = (float*)d_out;
    (void)in_sizes; (void)n_in; (void)out_size;

    cudaFuncSetAttribute(gemm_sk<256>, cudaFuncAttributeMaxDynamicSharedMemorySize, SMEM256);
    cudaFuncSetAttribute(gemm_sk<128>, cudaFuncAttributeMaxDynamicSharedMemorySize, SMEM128);

    fp16 *vidh, *vidl, *wt0h, *wt1h, *wt2h, *vh, *vl, *c2ah, *c2al;
    fp16 *uh, *ul, *wdh, *cdh, *fch, *sth, *stl, *gph;
    float *part, *att, *gsraw, *sall, *sc, *G, *un, *sn, *gn;
    cudaGetSymbolAddress((void**)&vidh, g_vidh); cudaGetSymbolAddress((void**)&vidl, g_vidl);
    cudaGetSymbolAddress((void**)&wt0h, g_wt0h);
    cudaGetSymbolAddress((void**)&wt1h, g_wt1h);
    cudaGetSymbolAddress((void**)&wt2h, g_wt2h);
    cudaGetSymbolAddress((void**)&vh, g_vh);     cudaGetSymbolAddress((void**)&vl, g_vl);
    cudaGetSymbolAddress((void**)&c2ah, g_c2ah); cudaGetSymbolAddress((void**)&c2al, g_c2al);
    cudaGetSymbolAddress((void**)&uh, g_uh);     cudaGetSymbolAddress((void**)&ul, g_ul);
    cudaGetSymbolAddress((void**)&wdh, g_wdh);
    cudaGetSymbolAddress((void**)&cdh, g_cdh);
    cudaGetSymbolAddress((void**)&fch, g_fch);
    cudaGetSymbolAddress((void**)&sth, g_sth);   cudaGetSymbolAddress((void**)&stl, g_stl);
    cudaGetSymbolAddress((void**)&gph, g_gph);
    cudaGetSymbolAddress((void**)&part, g_part);
    cudaGetSymbolAddress((void**)&att, g_att);
    cudaGetSymbolAddress((void**)&gsraw, g_gsraw);
    cudaGetSymbolAddress((void**)&sall, g_sall); cudaGetSymbolAddress((void**)&sc, g_sc);
    cudaGetSymbolAddress((void**)&G, g_G);       cudaGetSymbolAddress((void**)&un, g_un);
    cudaGetSymbolAddress((void**)&sn, g_sn);     cudaGetSymbolAddress((void**)&gn, g_gn);

    // 1..3: prep (conv0 GEMM stays launch #4 for the ncu capture slot)
    bigsplit_k<<<30208, 256>>>(video, vidh, vidl, words, wdh,
                               sent, sth, stl, cdw, cdh, fcw, fch);
    wsplit3_k<<<3072, 256>>>(c0w, wt0h, c1w, wt1h, c2w, wt2h);
    rownorm_k<<<64, 256>>>(sent, sn, 1024);

    // 4: conv0 GEMM: M=1024 N=1024 K=4096, S=4 Ks=1024 (128 CTAs)
    gemm_sk<256><<<dim3(8, 4, 4), 512, SMEM256>>>(vidh, vidl, wt0h, part, 1024, 4096, 1024,
        nullptr, nullptr, nullptr, nullptr, 0, 0, 1 << 20);

    gram_k<<<64, 256>>>(words, G);

    finish_k<true, true><<<4096, 256>>>(part, 4, 1048576, 1048576, c0b,
                                        nullptr, vh, vl, nullptr, nullptr);

    // conv1: M=256 N=1024 K=4096, S=16 Ks=256 (128 CTAs); dup into conv2 A view
    gemm_sk<256><<<dim3(8, 1, 16), 512, SMEM256>>>(vh, vl, wt1h, part, 1024, 4096, 256,
        nullptr, nullptr, nullptr, nullptr, 0, 0, 1 << 20);
    finish_k<true, true><<<1024, 256>>>(part, 16, 262144, 262144, c1b,
                                        nullptr, vh + 1048576, vl + 1048576, c2ah, c2al);

    // conv2: M=128 (64 valid + pad) N=1024 K=4096, S=16 Ks=256
    gemm_sk<128><<<dim3(8, 1, 16), 512, SMEM128>>>(c2ah, c2al, wt2h, part, 1024, 4096, 256,
        nullptr, nullptr, nullptr, nullptr, 0, 0, 1 << 20);
    finish_k<true, true><<<256, 256>>>(part, 16, 65536, 131072, c2b,
                                       nullptr, vh + 1310720, vl + 1310720, nullptr, nullptr);

    // conv1d (+ fc folded as y=11): N=1024, K=1024, S=2 Ks=512 (192 CTAs)
    gemm_sk<128><<<dim3(8, 12, 2), 512, SMEM128>>>(vh, vl, cdh, part, 1024, 1024, 512,
        vh + 1310720, vl + 1310720, fch,
        part + 1408 * 1024, 1024, CONV1D_SLICE, 11);
    finishrow2_k<<<1408, 256>>>(part, cdb, fcb, uh, ul, un, gph, gn);

    // att (+ gsraw folded as y=11,x=0): N=1280, K=1024, S=2 Ks=512 (222 active CTAs)
    gemm_sk<128><<<dim3(10, 12, 2), 512, SMEM128>>>(uh, ul, wdh, part, 1280, 1024, 512,
        sth, stl, gph,
        part + GS_OFF, 128, 16384, 11);
    finish_k<false, false><<<6720, 256>>>(part, 2, 1720320, ATT_SLICE, nullptr,
                                          att, nullptr, nullptr, nullptr, nullptr);
    finish_k<false, false><<<64, 256>>>(part + GS_OFF, 2, 16384, 16384, nullptr,
                                        gsraw, nullptr, nullptr, nullptr, nullptr);

    // fused sim + reductions
    sim_k<<<64, 672>>>(att, G, un, wmask, sall);
    scores_k<<<16, 256>>>(sall, sc, out);
    loss_k<<<1, 256>>>(sc, gsraw, sn, gn, out);
}

// round 15
// speedup vs baseline: 1.5066x; 1.1173x over previous
#include <cuda_runtime.h>
#include <cuda_fp16.h>
#include <math.h>
#include <stdint.h>

#define EPSF 1e-8f
#define MARGINF 0.2f
#define NATT 1280

typedef __half fp16;

__device__ __forceinline__ uint32_t h2u(__half2 h) {
    return *reinterpret_cast<uint32_t*>(&h);
}

// ======================= scratch (no allocation; zero-initialized) =======================
__device__ fp16 g_vidh[4194304], g_vidl[4194304];       // video split A (1024x4096)
__device__ fp16 g_wt0h[4194304];                        // conv0 weight T (B: hi only)
__device__ fp16 g_wt1h[4194304];                        // conv1 weight T
__device__ fp16 g_wt2h[4194304];                        // conv2 weight T
__device__ fp16 g_vh[1572864],   g_vl[1572864];         // conv outputs split A (rows 1344+ stay 0)
__device__ fp16 g_uh[1572864],   g_ul[1572864];         // u split A (rows 1344+ stay 0)
__device__ fp16 g_wdh[1310720];                         // words (B: hi only)
__device__ fp16 g_cdh[1048576];                         // conv1d w (B)
__device__ fp16 g_fch[1048576];                         // fc w (B)
__device__ fp16 g_sth[131072],   g_stl[131072];         // sentences split A + pad (128x1024)
__device__ fp16 g_gph[131072];                          // gpre (B: hi only; rows 64+ stay 0)
__device__ float g_part[4194304];                       // split-K partials
__device__ float g_att[1720320];                        // attention logits (1344x1280)
__device__ float g_gsraw[16384];                        // 128x128 (top 64x64 valid)
__device__ float g_sall[64 * 64 * 21];
__device__ float g_sc[4096];
__device__ float g_G[64 * 400];
__device__ float g_un[1344];
__device__ float g_sn[64];
__device__ float g_gn[64];

#define CONV1D_SLICE 1572864
#define ATT_SLICE    1966080
#define GS_OFF       3932160

// ======================= vectorized split kernels =======================
__device__ __forceinline__ void pack8(const float4& v0, const float4& v1,
                                      uint4& ho, uint4& lo_) {
    __half2 h0 = __floats2half2_rn(v0.x, v0.y);
    __half2 h1 = __floats2half2_rn(v0.z, v0.w);
    __half2 h2 = __floats2half2_rn(v1.x, v1.y);
    __half2 h3 = __floats2half2_rn(v1.z, v1.w);
    ho.x = h2u(h0); ho.y = h2u(h1); ho.z = h2u(h2); ho.w = h2u(h3);
    __half2 l0 = __floats2half2_rn(v0.x - __low2float(h0),  v0.y - __high2float(h0));
    __half2 l1 = __floats2half2_rn(v0.z - __low2float(h1),  v0.w - __high2float(h1));
    __half2 l2 = __floats2half2_rn(v1.x - __low2float(h2),  v1.y - __high2float(h2));
    __half2 l3 = __floats2half2_rn(v1.z - __low2float(h3),  v1.w - __high2float(h3));
    lo_.x = h2u(l0); lo_.y = h2u(l1); lo_.z = h2u(l2); lo_.w = h2u(l3);
}
__device__ __forceinline__ void split8A(const float* __restrict__ x, fp16* __restrict__ hi,
                                        fp16* __restrict__ lo, int idx, int n) {
    int i8 = idx * 8;
    float4 v0 = {0, 0, 0, 0}, v1 = {0, 0, 0, 0};
    if (i8 < n) { v0 = *(const float4*)(x + i8); v1 = *(const float4*)(x + i8 + 4); }
    uint4 ho, lw;
    pack8(v0, v1, ho, lw);
    *(uint4*)(hi + i8) = ho;
    *(uint4*)(lo + i8) = lw;
}
__device__ __forceinline__ void split8B(const float* __restrict__ x, fp16* __restrict__ hi,
                                        int idx, int n) {
    int i8 = idx * 8;
    float4 v0 = {0, 0, 0, 0}, v1 = {0, 0, 0, 0};
    if (i8 < n) { v0 = *(const float4*)(x + i8); v1 = *(const float4*)(x + i8 + 4); }
    uint4 ho;
    ho.x = h2u(__floats2half2_rn(v0.x, v0.y));
    ho.y = h2u(__floats2half2_rn(v0.z, v0.w));
    ho.z = h2u(__floats2half2_rn(v1.x, v1.y));
    ho.w = h2u(__floats2half2_rn(v1.z, v1.w));
    *(uint4*)(hi + i8) = ho;
}
__global__ void bigsplit_k(const float* __restrict__ video, fp16* __restrict__ vidh, fp16* __restrict__ vidl,
                           const float* __restrict__ words, fp16* __restrict__ wdh,
                           const float* __restrict__ sent, fp16* __restrict__ sth, fp16* __restrict__ stl,
                           const float* __restrict__ cdw, fp16* __restrict__ cdh,
                           const float* __restrict__ fcw, fp16* __restrict__ fch) {
    int b = blockIdx.x;
    if (b < 2048)       split8A(video, vidh, vidl, b * 256 + threadIdx.x, 4194304);
    else if (b < 2688)  split8B(words, wdh, (b - 2048) * 256 + threadIdx.x, 1310720);
    else if (b < 2752)  split8A(sent, sth, stl, (b - 2688) * 256 + threadIdx.x, 65536);
    else if (b < 3264)  split8B(cdw, cdh, (b - 2752) * 256 + threadIdx.x, 1048576);
    else                split8B(fcw, fch, (b - 3264) * 256 + threadIdx.x, 1048576);
}
// conv weight transpose (B side), smem staged
__global__ void wsplit3_k(const float* __restrict__ w0, fp16* __restrict__ h0,
                          const float* __restrict__ w1, fp16* __restrict__ h1,
                          const float* __restrict__ w2, fp16* __restrict__ h2) {
    __shared__ float ws[4096 + 128];
    int cv = blockIdx.x >> 10, o = blockIdx.x & 1023;
    const float* w = (cv == 0) ? w0 : (cv == 1) ? w1 : w2;
    fp16* hi = (cv == 0) ? h0 : (cv == 1) ? h1 : h2;
    const float* wo = w + (size_t)o * 4096;
    for (int q = threadIdx.x; q < 4096; q += blockDim.x)
        ws[q + (q >> 5)] = wo[q];
    __syncthreads();
    for (int q = threadIdx.x; q < 4096; q += blockDim.x) {
        int k = q >> 10, i = q & 1023;
        int a = i * 4 + k;
        hi[(size_t)o * 4096 + q] = __float2half(ws[a + (a >> 5)]);
    }
}

// ======================= mma.sync / cp.async helpers =======================
__device__ __forceinline__ uint32_t s2u(const void* p) {
    uint32_t a;
    asm("{ .reg .u64 t; cvta.to.shared.u64 t, %1; cvt.u32.u64 %0, t; }" : "=r"(a) : "l"(p));
    return a;
}
__device__ __forceinline__ void ldm4(uint32_t* r, uint32_t addr) {
    asm volatile("ldmatrix.sync.aligned.m8n8.x4.shared.b16 {%0,%1,%2,%3}, [%4];"
                 : "=r"(r[0]), "=r"(r[1]), "=r"(r[2]), "=r"(r[3]) : "r"(addr));
}
__device__ __forceinline__ void mma_fp16(float* c, const uint32_t* a, const uint32_t* b) {
    asm volatile("mma.sync.aligned.m16n8k16.row.col.f32.f16.f16.f32 "
                 "{%0,%1,%2,%3}, {%4,%5,%6,%7}, {%8,%9}, {%0,%1,%2,%3};"
                 : "+f"(c[0]), "+f"(c[1]), "+f"(c[2]), "+f"(c[3])
                 : "r"(a[0]), "r"(a[1]), "r"(a[2]), "r"(a[3]), "r"(b[0]), "r"(b[1]));
}
__device__ __forceinline__ void cp32(uint32_t s, const char* g) {
    asm volatile("cp.async.cg.shared.global [%0], [%1], 16;" :: "r"(s), "l"(g));
    asm volatile("cp.async.cg.shared.global [%0], [%1], 16;" :: "r"(s + 16), "l"(g + 16));
}
#define CP_COMMIT() asm volatile("cp.async.commit_group;" ::: "memory")
#define CP_WAIT(n)  asm volatile("cp.async.wait_group %0;" :: "n"(n) : "memory")

// ======================= fp16x2 HMMA split-K GEMM (R13, unchanged) =======================
template<int TM>
__global__ void __launch_bounds__(512)
gemm_sk(const fp16* __restrict__ Ah_, const fp16* __restrict__ Al_,
        const fp16* __restrict__ Bh_,
        float* __restrict__ P, int N, int K, int Ks,
        const fp16* A2h, const fp16* A2l, const fp16* B2h,
        float* P2, int N2, int stride2, int ySplit) {
    constexpr int WM = TM / 32;
    constexpr int WN = 16 / WM;
    constexpr int NT = 16 / WN;
    constexpr uint32_t SA = (uint32_t)TM * 80u;
    constexpr uint32_t SB = 128u * 80u;
    constexpr uint32_t STG = 2u * SA + SB;

    const bool alt = ((int)blockIdx.y >= ySplit);
    if (alt && ((int)blockIdx.x << 7) >= N2) return;

    extern __shared__ char smem[];
    const uint32_t sbase = s2u(smem);
    const int tid = threadIdx.x, lane = tid & 31, wid = tid >> 5;
    const int warp_m = wid % WM, warp_n = wid / WM;
    const int bn = blockIdx.x << 7;
    const int sl = blockIdx.z;
    const int bm = alt ? 0 : blockIdx.y * TM;
    const int Nn = alt ? N2 : N;
    const fp16* __restrict__ Ah = alt ? A2h : Ah_;
    const fp16* __restrict__ Al = alt ? A2l : Al_;
    const fp16* __restrict__ Bh = alt ? B2h : Bh_;
    float* Pout = alt ? (P2 + (size_t)sl * stride2)
                      : (P + (size_t)sl * ((size_t)gridDim.y * TM) * N);

    const size_t K2 = (size_t)K * 2;
    const size_t k0b = (size_t)sl * Ks * 2;
    const uint32_t coloff = (uint32_t)(tid & 1) * 32u;
    const bool doB = (tid < 256);

    const char *pA0, *pA1 = nullptr, *pB = nullptr;
    uint32_t sA0, sA1 = 0, sBo = 0;
    if (TM == 256) {
        int arow = tid >> 1;
        pA0 = (const char*)Ah + (size_t)(bm + arow) * K2 + coloff + k0b;
        sA0 = arow * 80u + coloff;
        pA1 = (const char*)Al + (size_t)(bm + arow) * K2 + coloff + k0b;
        sA1 = SA + arow * 80u + coloff;
        if (doB) {
            int brow = tid >> 1;
            pB = (const char*)Bh + (size_t)(bn + brow) * K2 + coloff + k0b;
            sBo = 2u * SA + brow * 80u + coloff;
        }
    } else {
        int arow = (tid >> 1) & 127;
        pA0 = (const char*)(tid < 256 ? Ah : Al) + (size_t)(bm + arow) * K2 + coloff + k0b;
        sA0 = (tid < 256 ? 0u : SA) + arow * 80u + coloff;
        if (doB) {
            int brow = tid >> 1;
            pB = (const char*)Bh + (size_t)(bn + brow) * K2 + coloff + k0b;
            sBo = 2u * SA + brow * 80u + coloff;
        }
    }

    const uint32_t a_off = (uint32_t)((warp_m * 32 + (lane & 15)) * 80 + (lane & 16));
    const uint32_t b_row = (uint32_t)(warp_n * (NT * 8) + (lane & 7) + ((lane & 16) ? 8 : 0));
    const uint32_t b_off = 2u * SA + b_row * 80u + ((lane & 8) ? 16u : 0u);

    float acc[2][NT][4];
#pragma unroll
    for (int mt = 0; mt < 2; mt++)
#pragma unroll
        for (int nt = 0; nt < NT; nt++)
#pragma unroll
            for (int q = 0; q < 4; q++) acc[mt][nt][q] = 0.f;

    const int nch = Ks >> 5;
    cp32(sbase + sA0, pA0);
    if (TM == 256) cp32(sbase + sA1, pA1);
    if (doB) cp32(sbase + sBo, pB);
    CP_COMMIT();
    if (nch > 1) {
        cp32(sbase + STG + sA0, pA0 + 64);
        if (TM == 256) cp32(sbase + STG + sA1, pA1 + 64);
        if (doB) cp32(sbase + STG + sBo, pB + 64);
        CP_COMMIT();
    }

    for (int c = 0; c < nch; c++) {
        if (c + 1 < nch) { CP_WAIT(1); } else { CP_WAIT(0); }
        __syncthreads();
        if (c + 2 < nch) {
            const size_t koff = (size_t)(c + 2) * 64;
            const uint32_t sb = sbase + (uint32_t)((c + 2) % 3) * STG;
            cp32(sb + sA0, pA0 + koff);
            if (TM == 256) cp32(sb + sA1, pA1 + koff);
            if (doB) cp32(sb + sBo, pB + koff);
            CP_COMMIT();
        }
        const uint32_t buf = sbase + (uint32_t)(c % 3) * STG;
#pragma unroll
        for (int ks = 0; ks < 2; ks++) {
            const uint32_t kb = (uint32_t)ks * 32u;
            uint32_t aH[2][4], aL[2][4], bT[NT][2];
#pragma unroll
            for (int mt = 0; mt < 2; mt++) {
                ldm4(aH[mt], buf + a_off + (uint32_t)(mt * 16) * 80u + kb);
                ldm4(aL[mt], buf + SA + a_off + (uint32_t)(mt * 16) * 80u + kb);
            }
#pragma unroll
            for (int g = 0; g < NT / 2; g++)
                ldm4(&bT[g * 2][0], buf + b_off + (uint32_t)(g * 16) * 80u + kb);
#pragma unroll
            for (int mt = 0; mt < 2; mt++)
#pragma unroll
                for (int nt = 0; nt < NT; nt++)
                    mma_fp16(acc[mt][nt], aH[mt], bT[nt]);
#pragma unroll
            for (int mt = 0; mt < 2; mt++)
#pragma unroll
                for (int nt = 0; nt < NT; nt++)
                    mma_fp16(acc[mt][nt], aL[mt], bT[nt]);
        }
    }

    const int r0 = (alt ? 0 : bm) + warp_m * 32 + (lane >> 2);
    const int c0 = bn + warp_n * (NT * 8) + (lane & 3) * 2;
#pragma unroll
    for (int mt = 0; mt < 2; mt++) {
#pragma unroll
        for (int nt = 0; nt < NT; nt++) {
            int col = c0 + nt * 8;
            float2 u0, u1;
            u0.x = acc[mt][nt][0]; u0.y = acc[mt][nt][1];
            u1.x = acc[mt][nt][2]; u1.y = acc[mt][nt][3];
            *(float2*)(Pout + (size_t)(r0 + mt * 16) * Nn + col) = u0;
            *(float2*)(Pout + (size_t)(r0 + mt * 16 + 8) * Nn + col) = u1;
        }
    }
}

// ======================= vectorized finish (4 elems/thread) =======================
template<bool RELU, bool BIAS>
__global__ void finish_k(const float* __restrict__ P, int S, int MNused, int MNfull,
                         const float* __restrict__ bias,
                         float* __restrict__ f32o,
                         fp16* __restrict__ hi, fp16* __restrict__ lo) {
    int i4 = (blockIdx.x * blockDim.x + threadIdx.x) * 4;
    if (i4 >= MNused) return;
    float4 a = *(const float4*)(P + i4);
    for (int s = 1; s < S; s++) {
        float4 b = *(const float4*)(P + (size_t)s * MNfull + i4);
        a.x += b.x; a.y += b.y; a.z += b.z; a.w += b.w;
    }
    if (BIAS) {
        float4 b = *(const float4*)(bias + (i4 & 1023));
        a.x += b.x; a.y += b.y; a.z += b.z; a.w += b.w;
    }
    if (RELU) {
        a.x = fmaxf(a.x, 0.f); a.y = fmaxf(a.y, 0.f);
        a.z = fmaxf(a.z, 0.f); a.w = fmaxf(a.w, 0.f);
    }
    if (f32o) *(float4*)(f32o + i4) = a;
    if (hi) {
        __half2 h0 = __floats2half2_rn(a.x, a.y);
        __half2 h1 = __floats2half2_rn(a.z, a.w);
        uint2 ho = {h2u(h0), h2u(h1)};
        *(uint2*)(hi + i4) = ho;
        __half2 l0 = __floats2half2_rn(a.x - __low2float(h0), a.y - __high2float(h0));
        __half2 l1 = __floats2half2_rn(a.z - __low2float(h1), a.w - __high2float(h1));
        uint2 lw = {h2u(l0), h2u(l1)};
        *(uint2*)(lo + i4) = lw;
    }
}

// merged finishrow: conv1d rows -> uh/ul/un ; fc rows -> gph + gn. S=2, vectorized.
__global__ void finishrow2_k(const float* __restrict__ P,
                             const float* __restrict__ cdb, const float* __restrict__ fcb,
                             fp16* __restrict__ uh, fp16* __restrict__ ul, float* __restrict__ un,
                             fp16* __restrict__ gph, float* __restrict__ gn) {
    int r = blockIdx.x;   // 0..1407
    int pr, orow;
    const float* bias;
    fp16 *oh, *ol;
    float* on;
    if (r < 1344) { pr = r; bias = cdb; oh = uh; ol = ul; on = un; orow = r; }
    else { int rf = r - 1344; pr = 1408 + rf; bias = fcb; oh = gph; ol = nullptr; on = gn; orow = rf; }
    const float* p = P + (size_t)pr * 1024;
    int k4 = threadIdx.x * 4;
    float4 a = *(const float4*)(p + k4);
    float4 b = *(const float4*)(p + CONV1D_SLICE + k4);
    float4 bv = *(const float4*)(bias + k4);
    a.x += b.x + bv.x; a.y += b.y + bv.y; a.z += b.z + bv.z; a.w += b.w + bv.w;
    __half2 h0 = __floats2half2_rn(a.x, a.y);
    __half2 h1 = __floats2half2_rn(a.z, a.w);
    uint2 ho = {h2u(h0), h2u(h1)};
    *(uint2*)(oh + (size_t)orow * 1024 + k4) = ho;
    if (ol) {
        __half2 l0 = __floats2half2_rn(a.x - __low2float(h0), a.y - __high2float(h0));
        __half2 l1 = __floats2half2_rn(a.z - __low2float(h1), a.w - __high2float(h1));
        uint2 lw = {h2u(l0), h2u(l1)};
        *(uint2*)(ol + (size_t)orow * 1024 + k4) = lw;
    }
    float sq = a.x * a.x + a.y * a.y + a.z * a.z + a.w * a.w;
    __shared__ float red[256];
    red[threadIdx.x] = sq; __syncthreads();
    for (int off = 128; off > 0; off >>= 1) {
        if (threadIdx.x < off) red[threadIdx.x] += red[threadIdx.x + off];
        __syncthreads();
    }
    if (threadIdx.x == 0) on[orow] = fmaxf(sqrtf(red[0]), EPSF);
}

// ======================= epilogue kernels =======================
__global__ void rownorm_k(const float* __restrict__ X, float* __restrict__ out, int K) {
    int r = blockIdx.x;
    const float* x = X + (size_t)r * K;
    float s = 0.f;
    for (int k = threadIdx.x; k < K; k += blockDim.x) { float v = x[k]; s += v * v; }
    __shared__ float red[256];
    red[threadIdx.x] = s; __syncthreads();
    for (int off = 128; off > 0; off >>= 1) {
        if (threadIdx.x < off) red[threadIdx.x] += red[threadIdx.x + off];
        __syncthreads();
    }
    if (threadIdx.x == 0) out[r] = fmaxf(sqrtf(red[0]), EPSF);
}

__global__ void gram_k(const float* __restrict__ words, float* __restrict__ G) {
    int i = blockIdx.x;
    int warp = threadIdx.x >> 5, lane = threadIdx.x & 31;
    const float4* base = (const float4*)(words + (size_t)i * 20480);
    for (int p = warp; p < 400; p += 8) {
        int w = p / 20, w2 = p % 20;
        const float4* x = base + w * 256;
        const float4* y = base + w2 * 256;
        float s = 0.f;
#pragma unroll
        for (int k = lane; k < 256; k += 32) {
            float4 a = x[k], b = y[k];
            s += a.x * b.x + a.y * b.y + a.z * b.z + a.w * b.w;
        }
        for (int off = 16; off; off >>= 1) s += __shfl_down_sync(0xffffffffu, s, off);
        if (lane == 0) G[i * 400 + p] = s;
    }
}

// 448 blocks x 192 threads: block (i, seg), item = seg*192 + tid
__global__ void __launch_bounds__(192)
sim_k(const float* __restrict__ att, const float* __restrict__ G,
      const float* __restrict__ un, const int* __restrict__ wmask,
      float* __restrict__ sall) {
    int i = blockIdx.x / 7, seg = blockIdx.x % 7;
    __shared__ float Gs[400];
    __shared__ float mk[20];
    for (int p = threadIdx.x; p < 400; p += 192) Gs[p] = G[i * 400 + p];
    if (threadIdx.x < 20)
        mk[threadIdx.x] = (wmask[i * 20 + threadIdx.x] > 0) ? 0.f : -1e30f;
    __syncthreads();
    int item = seg * 192 + threadIdx.x;
    int j = item / 21, t = item % 21;
    int r;
    if (t < 16)       r = j * 16 + t;
    else if (t < 20)  r = 1024 + j * 4 + (t - 16);
    else              r = 1280 + j;
    const float* arow = att + (size_t)r * NATT + i * 20;
    float a[20], am[20], e[20];
    float m = -1e38f;
#pragma unroll
    for (int w = 0; w < 20; w++) { a[w] = arow[w]; am[w] = a[w] + mk[w]; m = fmaxf(m, am[w]); }
    float s = 0.f;
#pragma unroll
    for (int w = 0; w < 20; w++) { e[w] = __expf(am[w] - m); s += e[w]; }
    float inv = 1.f / s;
    float num = 0.f;
#pragma unroll
    for (int w = 0; w < 20; w++) { e[w] *= inv; num += e[w] * a[w]; }
    float den2 = 0.f;
#pragma unroll
    for (int w = 0; w < 20; w++) {
        float q = 0.f;
#pragma unroll
        for (int w2 = 0; w2 < 20; w2++) q += e[w2] * Gs[w * 20 + w2];
        den2 += e[w] * q;
    }
    float sim = num / (un[r] * fmaxf(sqrtf(den2), EPSF));
    sall[((size_t)i * 64 + j) * 21 + t] = sim;
}

__global__ void scores_k(const float* __restrict__ sall, float* __restrict__ sc,
                         float* __restrict__ out) {
    int idx = blockIdx.x * blockDim.x + threadIdx.x;
    if (idx >= 4096) return;
    const float* p = sall + (size_t)idx * 21;
    float s = 0.f;
#pragma unroll
    for (int t = 0; t < 21; t++) s += p[t];
    sc[idx] = s * (1.f / 21.f);
    int i = idx >> 6, j = idx & 63;
    if (i == j) {
#pragma unroll
        for (int t = 0; t < 21; t++) out[1 + i * 21 + t] = p[t];
    }
}

__global__ void loss_k(const float* __restrict__ sc, const float* __restrict__ gs,
                       const float* __restrict__ sn, const float* __restrict__ gn,
                       float* __restrict__ out) {
    __shared__ float ds[64], dg[64], isn[64], ign[64];
    int tid = threadIdx.x;
    if (tid < 64) {
        ds[tid] = sc[tid * 65];
        isn[tid] = 1.f / sn[tid];
        ign[tid] = 1.f / gn[tid];
        dg[tid] = gs[tid * 129] * (1.f / (sn[tid] * gn[tid]));
    }
    __syncthreads();
    float acc = 0.f;
    for (int idx = tid; idx < 4096; idx += blockDim.x) {
        int i = idx >> 6, j = idx & 63;
        if (i == j) continue;
        float s = sc[idx];
        acc += fmaxf(MARGINF + s - ds[i], 0.f) + fmaxf(MARGINF + s - ds[j], 0.f);
        float g = gs[i * 128 + j] * isn[i] * ign[j];
        acc += fmaxf(MARGINF + g - dg[i], 0.f) + fmaxf(MARGINF + g - dg[j], 0.f);
    }
    __shared__ float red[256];
    red[tid] = acc; __syncthreads();
    for (int off = 128; off; off >>= 1) {
        if (tid < off) red[tid] += red[tid + off];
        __syncthreads();
    }
    if (tid == 0) out[0] = red[0] * (1.f / 64.f);
}

// ======================= launch =======================
#define SMEM256 153600
#define SMEM128 92160

extern "C" void kernel_launch(void* const* d_in, const int* in_sizes, int n_in,
                              void* d_out, int out_size) {
    const float* video = (const float*)d_in[0];
    const float* words = (const float*)d_in[1];
    const int*   wmask = (const int*)d_in[2];
    const float* sent  = (const float*)d_in[3];
    const float* c0w = (const float*)d_in[4];  const float* c0b = (const float*)d_in[5];
    const float* c1w = (const float*)d_in[6];  const float* c1b = (const float*)d_in[7];
    const float* c2w = (const float*)d_in[8];  const float* c2b = (const float*)d_in[9];
    const float* cdw = (const float*)d_in[10]; const float* cdb = (const float*)d_in[11];
    const float* fcw = (const float*)d_in[12]; const float* fcb = (const float*)d_in[13];
    float* out = (float*)d_out;
    (void)in_sizes; (void)n_in; (void)out_size;

    cudaFuncSetAttribute(gemm_sk<256>, cudaFuncAttributeMaxDynamicSharedMemorySize, SMEM256);
    cudaFuncSetAttribute(gemm_sk<128>, cudaFuncAttributeMaxDynamicSharedMemorySize, SMEM128);

    fp16 *vidh, *vidl, *wt0h, *wt1h, *wt2h, *vh, *vl;
    fp16 *uh, *ul, *wdh, *cdh, *fch, *sth, *stl, *gph;
    float *part, *att, *gsraw, *sall, *sc, *G, *un, *sn, *gn;
    cudaGetSymbolAddress((void**)&vidh, g_vidh); cudaGetSymbolAddress((void**)&vidl, g_vidl);
    cudaGetSymbolAddress((void**)&wt0h, g_wt0h);
    cudaGetSymbolAddress((void**)&wt1h, g_wt1h);
    cudaGetSymbolAddress((void**)&wt2h, g_wt2h);
    cudaGetSymbolAddress((void**)&vh, g_vh);     cudaGetSymbolAddress((void**)&vl, g_vl);
    cudaGetSymbolAddress((void**)&uh, g_uh);     cudaGetSymbolAddress((void**)&ul, g_ul);
    cudaGetSymbolAddress((void**)&wdh, g_wdh);
    cudaGetSymbolAddress((void**)&cdh, g_cdh);
    cudaGetSymbolAddress((void**)&fch, g_fch);
    cudaGetSymbolAddress((void**)&sth, g_sth);   cudaGetSymbolAddress((void**)&stl, g_stl);
    cudaGetSymbolAddress((void**)&gph, g_gph);
    cudaGetSymbolAddress((void**)&part, g_part);
    cudaGetSymbolAddress((void**)&att, g_att);
    cudaGetSymbolAddress((void**)&gsraw, g_gsraw);
    cudaGetSymbolAddress((void**)&sall, g_sall); cudaGetSymbolAddress((void**)&sc, g_sc);
    cudaGetSymbolAddress((void**)&G, g_G);       cudaGetSymbolAddress((void**)&un, g_un);
    cudaGetSymbolAddress((void**)&sn, g_sn);     cudaGetSymbolAddress((void**)&gn, g_gn);

    // 1..3: prep (conv0 GEMM stays launch #4 for the ncu capture slot)
    bigsplit_k<<<3776, 256>>>(video, vidh, vidl, words, wdh,
                              sent, sth, stl, cdw, cdh, fcw, fch);
    wsplit3_k<<<3072, 256>>>(c0w, wt0h, c1w, wt1h, c2w, wt2h);
    rownorm_k<<<64, 256>>>(sent, sn, 1024);

    // 4: conv0 GEMM: M=1024 N=1024 K=4096, S=4 Ks=1024 (128 CTAs)
    gemm_sk<256><<<dim3(8, 4, 4), 512, SMEM256>>>(vidh, vidl, wt0h, part, 1024, 4096, 1024,
        nullptr, nullptr, nullptr, nullptr, 0, 0, 1 << 20);

    gram_k<<<64, 256>>>(words, G);

    finish_k<true, true><<<1024, 256>>>(part, 4, 1048576, 1048576, c0b, nullptr, vh, vl);

    // conv1: M=256 N=1024 K=4096, S=16 Ks=256 (128 CTAs)
    gemm_sk<256><<<dim3(8, 1, 16), 512, SMEM256>>>(vh, vl, wt1h, part, 1024, 4096, 256,
        nullptr, nullptr, nullptr, nullptr, 0, 0, 1 << 20);
    finish_k<true, true><<<256, 256>>>(part, 16, 262144, 262144, c1b, nullptr,
                                       vh + 1048576, vl + 1048576);

    // conv2: A = direct 64x4096 re-view of v2 rows (pad rows read valid data, never finished)
    gemm_sk<128><<<dim3(8, 1, 16), 512, SMEM128>>>(vh + 1048576, vl + 1048576, wt2h,
        part, 1024, 4096, 256,
        nullptr, nullptr, nullptr, nullptr, 0, 0, 1 << 20);
    finish_k<true, true><<<64, 256>>>(part, 16, 65536, 131072, c2b, nullptr,
                                      vh + 1310720, vl + 1310720);

    // conv1d (+ fc folded as y=11): N=1024, K=1024, S=2 Ks=512 (192 CTAs)
    gemm_sk<128><<<dim3(8, 12, 2), 512, SMEM128>>>(vh, vl, cdh, part, 1024, 1024, 512,
        vh + 1310720, vl + 1310720, fch,
        part + 1408 * 1024, 1024, CONV1D_SLICE, 11);
    finishrow2_k<<<1408, 256>>>(part, cdb, fcb, uh, ul, un, gph, gn);

    // att (+ gsraw folded as y=11,x=0): N=1280, K=1024, S=2 Ks=512 (222 active CTAs)
    gemm_sk<128><<<dim3(10, 12, 2), 512, SMEM128>>>(uh, ul, wdh, part, 1280, 1024, 512,
        sth, stl, gph,
        part + GS_OFF, 128, 16384, 11);
    finish_k<false, false><<<1680, 256>>>(part, 2, 1720320, ATT_SLICE, nullptr,
                                          att, nullptr, nullptr);
    finish_k<false, false><<<16, 256>>>(part + GS_OFF, 2, 16384, 16384, nullptr,
                                        gsraw, nullptr, nullptr);

    // fused sim + reductions
    sim_k<<<448, 192>>>(att, G, un, wmask, sall);
    scores_k<<<16, 256>>>(sall, sc, out);
    loss_k<<<1, 256>>>(sc, gsraw, sn, gn, out);
}